// round 9
// baseline (speedup 1.0000x reference)
#include <cuda_runtime.h>
#include <math.h>

#define NB 296
#define NT 256
#define NROWS 256      // B*S
#define BBS 128        // S
#define DD 128
#define FF 512
#define VV 1024
#define DK 32
#define LL 2

// ---------------- device scratch ----------------
__device__ float g_x[NROWS*DD];
__device__ float g_qkv[NROWS*384];
__device__ float g_att[NROWS*DD];
__device__ float g_ff[NROWS*FF];
__device__ float g_ffp[4][NROWS*DD];
// transformed weights, N-MAJOR (original layout, elementwise f):
__device__ float g_twqkv[LL][3*DD*DD];   // [l][seg*16384 + n*128 + k], seg q/k/v
__device__ float g_two[LL*DD*DD];        // [l*16384 + n*128 + k]
__device__ float g_tw1[LL*FF*DD];        // [l*65536 + n*128 + k]
__device__ float g_tw2[LL*DD*FF];        // [l*65536 + n*512 + k]
__device__ float g_twout[VV*DD];         // [n*128 + k]
__device__ unsigned g_count;
__device__ unsigned g_gen;

struct Params {
    const int* tokens; const float* emb; const float* pos;
    const float* Wq; const float* bq; const float* Wk; const float* bk;
    const float* Wv; const float* bv; const float* Wo; const float* bo;
    const float* W1; const float* b1; const float* W2; const float* b2;
    const float* g1; const float* be1; const float* g2; const float* be2;
    const float* Wout; const float* bout;
    float* out;
};

// ---------------- l_mul elementwise transform (bit-twiddled) ----------------
// Reference: e = floor(log2|x|)+1; m = x*2^-e; r = round(m*8); f = r*2^(2e-3).
// For normals floor(log2|x|) = rawexp-127 exactly -> e = rawexp-126.
__device__ __forceinline__ float lmul_f(float x) {
    unsigned bits = __float_as_uint(x);
    int expo = (int)((bits >> 23) & 0xffu);
    if (expo == 0) return 0.0f;                 // zero or denormal
    int e = expo - 126;
    if (e < -40) return 0.0f;
    float m = __int_as_float((bits & 0x807fffffu) | (126u << 23));  // x*2^-e exact
    float r = rintf(m * 8.0f);                  // round-half-even
    return r * __int_as_float((unsigned)(2*e - 3 + 127) << 23);    // exact 2^(2e-3)
}

__device__ __forceinline__ float4 lmul_f4(float4 v) {
    float4 o;
    o.x = lmul_f(v.x); o.y = lmul_f(v.y); o.z = lmul_f(v.z); o.w = lmul_f(v.w);
    return o;
}

// ---------------- grid barrier ----------------
__device__ __forceinline__ void gbar() {
    __syncthreads();
    if (threadIdx.x == 0) {
        __threadfence();
        unsigned gen = *((volatile unsigned*)&g_gen);
        if (atomicAdd(&g_count, 1u) == NB - 1u) {
            atomicExch(&g_count, 0u);
            __threadfence();
            atomicExch(&g_gen, gen + 1u);
        } else {
            while (*((volatile unsigned*)&g_gen) == gen) __nanosleep(20);
        }
        __threadfence();
    }
    __syncthreads();
}

// ---------------- phase 0: elementwise weight transform + embed --------------
__device__ void transform_all(const Params* __restrict__ P) {
    const int t0 = blockIdx.x * NT + threadIdx.x;
    const int STEP = NB * NT;
    // embedding + positional
    for (int i = t0; i < NROWS*DD; i += STEP) {
        int row = i >> 7, d = i & 127;
        int s = row & (BBS - 1);
        g_x[i] = P->emb[P->tokens[row]*DD + d] + P->pos[s*DD + d];
    }
    // QKV (elementwise, per-segment placement)
    for (int i4 = t0; i4 < LL*DD*DD/4; i4 += STEP) {
        int i = i4*4; int l = i >> 14; int off = i & 16383;
        *(float4*)&g_twqkv[l][off] = lmul_f4(*(const float4*)&P->Wq[i]);
    }
    for (int i4 = t0; i4 < LL*DD*DD/4; i4 += STEP) {
        int i = i4*4; int l = i >> 14; int off = i & 16383;
        *(float4*)&g_twqkv[l][16384 + off] = lmul_f4(*(const float4*)&P->Wk[i]);
    }
    for (int i4 = t0; i4 < LL*DD*DD/4; i4 += STEP) {
        int i = i4*4; int l = i >> 14; int off = i & 16383;
        *(float4*)&g_twqkv[l][32768 + off] = lmul_f4(*(const float4*)&P->Wv[i]);
    }
    // flat elementwise maps
    for (int i4 = t0; i4 < LL*DD*DD/4; i4 += STEP)
        ((float4*)g_two)[i4] = lmul_f4(((const float4*)P->Wo)[i4]);
    for (int i4 = t0; i4 < LL*FF*DD/4; i4 += STEP)
        ((float4*)g_tw1)[i4] = lmul_f4(((const float4*)P->W1)[i4]);
    for (int i4 = t0; i4 < LL*DD*FF/4; i4 += STEP)
        ((float4*)g_tw2)[i4] = lmul_f4(((const float4*)P->W2)[i4]);
    for (int i4 = t0; i4 < VV*DD/4; i4 += STEP)
        ((float4*)g_twout)[i4] = lmul_f4(((const float4*)P->Wout)[i4]);
}

// ---------------- GEMM tile: (RPT*4) rows x 64 cols, K-chunk = 128 -----------
// Weights N-MAJOR: thread owning col c reads its weight row with float4.
// 256 threads: c = tid&63, g = tid>>6 -> rows g*RPT..g*RPT+RPT-1
template<int RPT>
__device__ __forceinline__ void gemm_nm(
    const float* __restrict__ X, int ldx, int kbeg,
    const float* __restrict__ W, int ldw,   // W[n*ldw + k]
    const float* __restrict__ bias,         // [c]; may be null
    int relu,
    float* __restrict__ Y, int ldy,
    int row0, int col0, float* __restrict__ xs /* (RPT*4)*132 */)
{
    const int ROWS = RPT * 4;
    const int tid = threadIdx.x;
    // stage f(X) rows with float4
    #pragma unroll
    for (int i = 0; i < ROWS*32/NT; ++i) {
        int idx = tid + i*NT;                // 0..ROWS*32-1
        int r = idx >> 5, k4 = (idx & 31) * 4;
        float4 v = lmul_f4(*(const float4*)(X + (size_t)(row0 + r)*ldx + kbeg + k4));
        xs[r*132 + k4 + 0] = v.x;
        xs[r*132 + k4 + 1] = v.y;
        xs[r*132 + k4 + 2] = v.z;
        xs[r*132 + k4 + 3] = v.w;
    }
    __syncthreads();
    const int c = tid & 63;
    const int g = tid >> 6;
    const float* wp = W + (size_t)(col0 + c)*ldw + kbeg;
    const float* xb = xs + g*RPT*132;
    float acc[RPT];
    #pragma unroll
    for (int j = 0; j < RPT; ++j) acc[j] = 0.f;
    #pragma unroll
    for (int kc = 0; kc < 128; kc += 32) {
        float4 w4[8];
        #pragma unroll
        for (int j = 0; j < 8; ++j) w4[j] = *(const float4*)(wp + kc + j*4);
        #pragma unroll
        for (int j = 0; j < 8; ++j) {
            #pragma unroll
            for (int r = 0; r < RPT; ++r) {
                float4 v = *(const float4*)(xb + r*132 + kc + j*4);
                acc[r] = fmaf(v.x, w4[j].x, acc[r]);
                acc[r] = fmaf(v.y, w4[j].y, acc[r]);
                acc[r] = fmaf(v.z, w4[j].z, acc[r]);
                acc[r] = fmaf(v.w, w4[j].w, acc[r]);
            }
        }
    }
    float b = bias ? bias[c] : 0.f;
    #pragma unroll
    for (int j = 0; j < RPT; ++j) {
        float a = acc[j] + b;
        if (relu) a = fmaxf(a, 0.f);
        Y[(size_t)(row0 + g*RPT + j)*ldy + col0 + c] = a;
    }
    __syncthreads();
}

// ---------------- attention tile: (b, h, 4-query block) ----------------------
__device__ void attn_tile(
    const float* __restrict__ qkv, float* __restrict__ attout,
    int b, int h, int qb, float* __restrict__ sm)
{
    float* ksh = sm;               // 128*33 = 4224
    float* vsh = sm + 4224;        // 128*33
    float* qsh = sm + 8448;        // 4*32 = 128
    float* psh = sm + 8576;        // 4*128 = 512
    const int tid = threadIdx.x;
    #pragma unroll
    for (int i = 0; i < 4; ++i) {
        int idx = tid + i*NT;       // 0..1023 = 128 rows x 8 float4
        int j = idx >> 3, d4 = (idx & 7) * 4;
        const float* base = qkv + (size_t)(b*BBS + j)*384 + h*DK + d4;
        float4 kk = *(const float4*)(base + 128);
        float4 vv = *(const float4*)(base + 256);
        float* kd = ksh + j*33 + d4;
        kd[0] = kk.x; kd[1] = kk.y; kd[2] = kk.z; kd[3] = kk.w;
        float* vd = vsh + j*33 + d4;
        vd[0] = vv.x; vd[1] = vv.y; vd[2] = vv.z; vd[3] = vv.w;
    }
    if (tid < 128) {
        int qi = tid >> 5, d = tid & 31;
        qsh[tid] = qkv[(size_t)(b*BBS + qb*4 + qi)*384 + h*DK + d];
    }
    __syncthreads();
    const int wid = tid >> 5, lane = tid & 31;
    if (wid < 4) {
        const int q = qb*4 + wid;
        float qr[32];
        #pragma unroll
        for (int d = 0; d < 32; d += 4) {
            float4 t = *(const float4*)(qsh + wid*32 + d);
            qr[d] = t.x; qr[d+1] = t.y; qr[d+2] = t.z; qr[d+3] = t.w;
        }
        const float* k0 = ksh + (lane     )*33;
        const float* k1 = ksh + (lane + 32)*33;
        const float* k2 = ksh + (lane + 64)*33;
        const float* k3 = ksh + (lane + 96)*33;
        float s0 = 0.f, s1 = 0.f, s2 = 0.f, s3 = 0.f;
        #pragma unroll
        for (int d = 0; d < 32; ++d) {
            float qd = qr[d];
            s0 = fmaf(qd, k0[d], s0);
            s1 = fmaf(qd, k1[d], s1);
            s2 = fmaf(qd, k2[d], s2);
            s3 = fmaf(qd, k3[d], s3);
        }
        const float scale = 0.17677669529663687f;  // 1/sqrt(32)
        s0 *= scale; s1 *= scale; s2 *= scale; s3 *= scale;
        float m = fmaxf(fmaxf(s0, s1), fmaxf(s2, s3));
        #pragma unroll
        for (int o = 16; o; o >>= 1) m = fmaxf(m, __shfl_xor_sync(0xffffffffu, m, o));
        float p0 = __expf(s0 - m), p1 = __expf(s1 - m), p2 = __expf(s2 - m), p3 = __expf(s3 - m);
        float lsum = p0 + p1 + p2 + p3;
        #pragma unroll
        for (int o = 16; o; o >>= 1) lsum += __shfl_xor_sync(0xffffffffu, lsum, o);
        float* pp = psh + wid*128;
        pp[lane     ] = p0;
        pp[lane + 32] = p1;
        pp[lane + 64] = p2;
        pp[lane + 96] = p3;
        __syncwarp();
        float o0 = 0.f, o1 = 0.f, o2 = 0.f, o3 = 0.f;
        #pragma unroll 8
        for (int j = 0; j < 128; j += 4) {
            o0 = fmaf(pp[j+0], vsh[(j+0)*33 + lane], o0);
            o1 = fmaf(pp[j+1], vsh[(j+1)*33 + lane], o1);
            o2 = fmaf(pp[j+2], vsh[(j+2)*33 + lane], o2);
            o3 = fmaf(pp[j+3], vsh[(j+3)*33 + lane], o3);
        }
        attout[(size_t)(b*BBS + q)*DD + h*DK + lane] = ((o0 + o1) + (o2 + o3)) / lsum;
    }
    __syncthreads();
}

// ---------------- O-proj + residual + LN1 (4 rows/block, 64 blocks) ----------
__device__ void oproj_ln(
    const float* __restrict__ att, const float* __restrict__ W,  // n-major [n*128+k]
    const float* __restrict__ bo, const float* __restrict__ g1,
    const float* __restrict__ be1, float* __restrict__ x,
    float* __restrict__ sm)
{
    const int row0 = blockIdx.x * 4;
    float* as   = sm;          // 4*132
    float* vals = sm + 544;    // 4*132
    float* st   = sm + 1088;   // 8
    const int tid = threadIdx.x;
    if (tid < 128) {            // 4 rows x 32 float4
        int r = tid >> 5, k4 = (tid & 31) * 4;
        float4 v = lmul_f4(*(const float4*)(att + (row0 + r)*DD + k4));
        as[r*132 + k4 + 0] = v.x;
        as[r*132 + k4 + 1] = v.y;
        as[r*132 + k4 + 2] = v.z;
        as[r*132 + k4 + 3] = v.w;
    }
    __syncthreads();
    const int c = tid & 127, rg = tid >> 7;       // rows rg*2, rg*2+1
    const float* x0p = as + (rg*2    )*132;
    const float* x1p = as + (rg*2 + 1)*132;
    const float* wp = W + (size_t)c * DD;
    float a0 = 0.f, a1 = 0.f;
    #pragma unroll
    for (int kc = 0; kc < 128; kc += 32) {
        float4 w4[8];
        #pragma unroll
        for (int j = 0; j < 8; ++j) w4[j] = *(const float4*)(wp + kc + j*4);
        #pragma unroll
        for (int j = 0; j < 8; ++j) {
            float4 v0 = *(const float4*)(x0p + kc + j*4);
            float4 v1 = *(const float4*)(x1p + kc + j*4);
            a0 = fmaf(v0.x, w4[j].x, a0); a1 = fmaf(v1.x, w4[j].x, a1);
            a0 = fmaf(v0.y, w4[j].y, a0); a1 = fmaf(v1.y, w4[j].y, a1);
            a0 = fmaf(v0.z, w4[j].z, a0); a1 = fmaf(v1.z, w4[j].z, a1);
            a0 = fmaf(v0.w, w4[j].w, a0); a1 = fmaf(v1.w, w4[j].w, a1);
        }
    }
    float b = bo[c];
    const int r0 = row0 + rg*2, r1 = r0 + 1;
    float v0 = x[r0*DD + c] + a0 + b;
    float v1 = x[r1*DD + c] + a1 + b;
    vals[(rg*2    )*132 + c] = v0;
    vals[(rg*2 + 1)*132 + c] = v1;
    __syncthreads();
    const int wid = tid >> 5, lane = tid & 31;
    if (wid < 4) {
        float s = 0.f, sq = 0.f;
        #pragma unroll
        for (int i = 0; i < 4; ++i) {
            float v = vals[wid*132 + lane + i*32];
            s += v; sq = fmaf(v, v, sq);
        }
        #pragma unroll
        for (int o = 16; o; o >>= 1) {
            s  += __shfl_xor_sync(0xffffffffu, s, o);
            sq += __shfl_xor_sync(0xffffffffu, sq, o);
        }
        if (lane == 0) {
            float mean = s * (1.f/128.f);
            float var  = sq * (1.f/128.f) - mean*mean;
            st[wid*2]     = mean;
            st[wid*2 + 1] = rsqrtf(var + 1e-5f);
        }
    }
    __syncthreads();
    {
        float gm = g1[c], bb = be1[c];
        float m0 = st[(rg*2)*2],     rs0 = st[(rg*2)*2 + 1];
        float m1 = st[(rg*2+1)*2],   rs1 = st[(rg*2+1)*2 + 1];
        x[r0*DD + c] = (v0 - m0)*rs0*gm + bb;
        x[r1*DD + c] = (v1 - m1)*rs1*gm + bb;
    }
    __syncthreads();
}

// ---------------- FF2 partial combine + bias + residual + LN2 -----------------
__device__ void ff2_ln(
    const float* __restrict__ b2, const float* __restrict__ g2,
    const float* __restrict__ be2, float* __restrict__ x,
    float* __restrict__ sm)
{
    float* vals = sm;         // 2*132
    float* st   = sm + 272;   // 4
    const int tid = threadIdx.x;
    const int c = tid & 127, rg = tid >> 7;
    const int row = blockIdx.x*2 + rg;
    float v = x[row*DD + c] + b2[c];
    #pragma unroll
    for (int ks = 0; ks < 4; ++ks) v += g_ffp[ks][row*DD + c];
    vals[rg*132 + c] = v;
    __syncthreads();
    const int wid = tid >> 5, lane = tid & 31;
    if (wid < 2) {
        float s = 0.f, sq = 0.f;
        #pragma unroll
        for (int i = 0; i < 4; ++i) {
            float t = vals[wid*132 + lane + i*32];
            s += t; sq = fmaf(t, t, sq);
        }
        #pragma unroll
        for (int o = 16; o; o >>= 1) {
            s  += __shfl_xor_sync(0xffffffffu, s, o);
            sq += __shfl_xor_sync(0xffffffffu, sq, o);
        }
        if (lane == 0) {
            float mean = s * (1.f/128.f);
            float var  = sq * (1.f/128.f) - mean*mean;
            st[wid*2]     = mean;
            st[wid*2 + 1] = rsqrtf(var + 1e-5f);
        }
    }
    __syncthreads();
    x[row*DD + c] = (v - st[rg*2])*st[rg*2 + 1]*g2[c] + be2[c];
    __syncthreads();
}

// ---------------- the one persistent kernel ----------------
__global__ void __launch_bounds__(NT, 2) model_kernel(Params P) {
    __shared__ __align__(16) float sm[9216];
    const int bid = blockIdx.x;

    // P0: elementwise transforms + embedding (coalesced float4)
    transform_all(&P);
    gbar();

    for (int l = 0; l < LL; ++l) {
        // P1: QKV fused GEMM — 96 tiles (16 rowtiles(16r) x 6 col64)
        if (bid < 96) {
            int rt = bid & 15, ct = bid >> 4;     // ct 0..5
            int col0 = ct * 64;
            int seg = col0 >> 7;                  // 0..2
            const float* segb = (seg == 0 ? P.bq : seg == 1 ? P.bk : P.bv)
                                + l*DD + (col0 & 127);
            gemm_nm<4>(g_x, DD, 0, g_twqkv[l], DD, segb, 0,
                       g_qkv, 384, rt*16, col0, sm);
        }
        gbar();

        // P2: attention — 256 tiles (b, h, 4-query block)
        if (bid < 256) {
            int b = bid >> 7, h = (bid >> 5) & 3, qb = bid & 31;
            attn_tile(g_qkv, g_att, b, h, qb, sm);
        }
        gbar();

        // P3: O-proj + residual + LN1 — 64 blocks
        if (bid < 64) {
            oproj_ln(g_att, g_two + l*DD*DD, P.bo + l*DD, P.g1 + l*DD,
                     P.be1 + l*DD, g_x, sm);
        }
        gbar();

        // P4: FF1 + relu — 128 tiles (16 rowtiles(16r) x 8 col64)
        if (bid < 128) {
            int rt = bid & 15, ct = bid >> 4;     // ct 0..7
            gemm_nm<4>(g_x, DD, 0, g_tw1 + l*FF*DD, DD, P.b1 + l*FF + ct*64, 1,
                       g_ff, FF, rt*16, ct*64, sm);
        }
        gbar();

        // P5: FF2 k-split partials — 128 tiles (16 rt x 2 col64 x 4 k-chunks)
        if (bid < 128) {
            int rt = bid & 15, ct = (bid >> 4) & 1, kc = bid >> 5;
            gemm_nm<4>(g_ff, FF, kc*128, g_tw2 + l*DD*FF, FF, (const float*)0, 0,
                       g_ffp[kc], DD, rt*16, ct*64, sm);
        }
        gbar();

        // P6: partial sum + bias + residual + LN2 — 128 blocks
        if (bid < 128) {
            ff2_ln(P.b2 + l*DD, P.g2 + l*DD, P.be2 + l*DD, g_x, sm);
        }
        gbar();
    }

    // P7: final vocab projection — 128 tiles (8 rowtiles(32r) x 16 col64)
    if (bid < 128) {
        int rt = bid & 7, ct = bid >> 3;
        gemm_nm<8>(g_x, DD, 0, g_twout, DD, P.bout + ct*64, 0,
                   P.out, VV, rt*32, ct*64, sm);
    }
}

extern "C" void kernel_launch(void* const* d_in, const int* in_sizes, int n_in,
                              void* d_out, int out_size) {
    Params P;
    P.tokens = (const int*)  d_in[0];
    P.emb    = (const float*)d_in[1];
    P.pos    = (const float*)d_in[2];
    P.Wq     = (const float*)d_in[3];
    P.bq     = (const float*)d_in[4];
    P.Wk     = (const float*)d_in[5];
    P.bk     = (const float*)d_in[6];
    P.Wv     = (const float*)d_in[7];
    P.bv     = (const float*)d_in[8];
    P.Wo     = (const float*)d_in[9];
    P.bo     = (const float*)d_in[10];
    P.W1     = (const float*)d_in[11];
    P.b1     = (const float*)d_in[12];
    P.W2     = (const float*)d_in[13];
    P.b2     = (const float*)d_in[14];
    P.g1     = (const float*)d_in[15];
    P.be1    = (const float*)d_in[16];
    P.g2     = (const float*)d_in[17];
    P.be2    = (const float*)d_in[18];
    P.Wout   = (const float*)d_in[19];
    P.bout   = (const float*)d_in[20];
    P.out    = (float*)d_out;

    model_kernel<<<NB, NT>>>(P);
}

// round 10
// speedup vs baseline: 1.4518x; 1.4518x over previous
#include <cuda_runtime.h>
#include <math.h>

#define NB 296
#define NT 256
#define NROWS 256      // B*S
#define BBS 128        // S
#define DD 128
#define FF 512
#define VV 1024
#define DK 32
#define LL 2

// ---------------- device scratch ----------------
__device__ float g_x[NROWS*DD];
__device__ float g_qkv[NROWS*384];
__device__ float g_att[NROWS*DD];
__device__ float g_ff[NROWS*FF];
__device__ float g_ffp[4][NROWS*DD];
// transformed weights, K-MAJOR: tw[k*N + n]  (coalesced over n)
__device__ float g_twqkv[LL][DD*384];
__device__ float g_two[LL][DD*DD];
__device__ float g_tw1[LL][DD*FF];
__device__ float g_tw2[LL][FF*DD];
__device__ float g_twout[DD*VV];
__device__ unsigned g_count;
__device__ unsigned g_gen;

struct Params {
    const int* tokens; const float* emb; const float* pos;
    const float* Wq; const float* bq; const float* Wk; const float* bk;
    const float* Wv; const float* bv; const float* Wo; const float* bo;
    const float* W1; const float* b1; const float* W2; const float* b2;
    const float* g1; const float* be1; const float* g2; const float* be2;
    const float* Wout; const float* bout;
    float* out;
};

// ---------------- l_mul elementwise transform (bit-twiddled) ----------------
// Reference: e = floor(log2|x|)+1; m = x*2^-e; r = round(m*8); f = r*2^(2e-3).
__device__ __forceinline__ float lmul_f(float x) {
    unsigned bits = __float_as_uint(x);
    int expo = (int)((bits >> 23) & 0xffu);
    if (expo == 0) return 0.0f;                 // zero or denormal
    int e = expo - 126;
    if (e < -40) return 0.0f;
    float m = __int_as_float((bits & 0x807fffffu) | (126u << 23));  // x*2^-e exact
    float r = rintf(m * 8.0f);                  // round-half-even
    return r * __int_as_float((unsigned)(2*e - 3 + 127) << 23);    // exact 2^(2e-3)
}

__device__ __forceinline__ float4 lmul_f4(float4 v) {
    float4 o;
    o.x = lmul_f(v.x); o.y = lmul_f(v.y); o.z = lmul_f(v.z); o.w = lmul_f(v.w);
    return o;
}

// ---------------- grid barrier ----------------
__device__ __forceinline__ void gbar() {
    __syncthreads();
    if (threadIdx.x == 0) {
        __threadfence();
        unsigned gen = *((volatile unsigned*)&g_gen);
        if (atomicAdd(&g_count, 1u) == NB - 1u) {
            atomicExch(&g_count, 0u);
            __threadfence();
            atomicExch(&g_gen, gen + 1u);
        } else {
            while (*((volatile unsigned*)&g_gen) == gen) __nanosleep(20);
        }
        __threadfence();
    }
    __syncthreads();
}

// ---------------- phase 0: weight transform (to k-major) + embed ------------
__device__ void transform_all(const Params* __restrict__ P) {
    const int t0 = blockIdx.x * NT + threadIdx.x;
    const int STEP = NB * NT;
    for (int i = t0; i < LL*DD*384; i += STEP) {
        int l = i / (DD*384); int r = i - l*(DD*384);
        int k = r / 384, n = r - k*384;
        const float* src; int nn;
        if (n < 128)      { src = P->Wq + l*DD*DD; nn = n; }
        else if (n < 256) { src = P->Wk + l*DD*DD; nn = n - 128; }
        else              { src = P->Wv + l*DD*DD; nn = n - 256; }
        g_twqkv[l][k*384 + n] = lmul_f(src[nn*DD + k]);
    }
    for (int i = t0; i < LL*DD*DD; i += STEP) {
        int l = i / (DD*DD); int r = i - l*(DD*DD);
        int k = r >> 7, n = r & 127;
        g_two[l][k*DD + n] = lmul_f(P->Wo[l*DD*DD + n*DD + k]);
    }
    for (int i = t0; i < LL*DD*FF; i += STEP) {
        int l = i / (DD*FF); int r = i - l*(DD*FF);
        int k = r >> 9, n = r & 511;
        g_tw1[l][k*FF + n] = lmul_f(P->W1[l*FF*DD + n*DD + k]);
    }
    for (int i = t0; i < LL*FF*DD; i += STEP) {
        int l = i / (FF*DD); int r = i - l*(FF*DD);
        int k = r >> 7, n = r & 127;
        g_tw2[l][k*DD + n] = lmul_f(P->W2[l*DD*FF + n*FF + k]);
    }
    for (int i = t0; i < DD*VV; i += STEP) {
        int k = i >> 10, n = i & 1023;
        g_twout[k*VV + n] = lmul_f(P->Wout[n*DD + k]);
    }
    for (int i = t0; i < NROWS*DD; i += STEP) {
        int row = i >> 7, d = i & 127;
        int s = row & (BBS - 1);
        g_x[i] = P->emb[P->tokens[row]*DD + d] + P->pos[s*DD + d];
    }
}

// ---------------- GEMM tile: (RPT*4) rows x 64 cols, K-chunk = 128 -----------
// MODE 0: stage f(X rows) plainly.
// MODE 1: rows come from g_x + b2 + sum(g_ffp) -> LN2 (warp-local) -> write
//         g_x (redundant identical across col-tiles) and stage f(LN2 row).
// Weights K-MAJOR (coalesced over n); batched scalar loads (proven R7 core).
template<int RPT, int MODE>
__device__ __forceinline__ void gemm_kM(
    const float* __restrict__ X, int ldx, int kbeg,
    const float* __restrict__ W, int N,
    const float* __restrict__ bias, int relu,
    const float* __restrict__ b2, const float* __restrict__ g2,
    const float* __restrict__ be2,
    float* __restrict__ Y, int ldy,
    int row0, int col0, float* __restrict__ xs /* (RPT*4)*132 */)
{
    const int ROWS = RPT * 4;
    const int tid = threadIdx.x;
    const int lane = tid & 31;
    // staging: one warp per row, float4 per lane
    #pragma unroll
    for (int i = 0; i < ROWS/8; ++i) {
        int r = (tid >> 5) + i*8;
        int k4 = lane * 4;
        if (MODE == 0) {
            float4 v = lmul_f4(*(const float4*)(X + (size_t)(row0 + r)*ldx + kbeg + k4));
            *(float4*)(xs + r*132 + k4) = v;
        } else {
            const int grow = row0 + r;
            float4 u = *(const float4*)(g_x + grow*DD + k4);
            float4 bb = *(const float4*)(b2 + k4);
            u.x += bb.x; u.y += bb.y; u.z += bb.z; u.w += bb.w;
            #pragma unroll
            for (int ks = 0; ks < 4; ++ks) {
                float4 p = *(const float4*)(g_ffp[ks] + grow*DD + k4);
                u.x += p.x; u.y += p.y; u.z += p.z; u.w += p.w;
            }
            float s  = (u.x + u.y) + (u.z + u.w);
            float sq = fmaf(u.x, u.x, fmaf(u.y, u.y, fmaf(u.z, u.z, u.w*u.w)));
            #pragma unroll
            for (int o = 16; o; o >>= 1) {
                s  += __shfl_xor_sync(0xffffffffu, s, o);
                sq += __shfl_xor_sync(0xffffffffu, sq, o);
            }
            float mean = s * (1.f/128.f);
            float rs = rsqrtf(sq * (1.f/128.f) - mean*mean + 1e-5f);
            float4 gv  = *(const float4*)(g2 + k4);
            float4 bev = *(const float4*)(be2 + k4);
            float4 ln;
            ln.x = (u.x - mean)*rs*gv.x + bev.x;
            ln.y = (u.y - mean)*rs*gv.y + bev.y;
            ln.z = (u.z - mean)*rs*gv.z + bev.z;
            ln.w = (u.w - mean)*rs*gv.w + bev.w;
            *(float4*)(g_x + grow*DD + k4) = ln;      // identical across col-tiles
            *(float4*)(xs + r*132 + k4) = lmul_f4(ln);
        }
    }
    __syncthreads();
    const int c = tid & 63;
    const int g = tid >> 6;
    const float* wp = W + (size_t)kbeg * N + col0 + c;
    const float* xb = xs + g*RPT*132;
    float acc[RPT];
    #pragma unroll
    for (int j = 0; j < RPT; ++j) acc[j] = 0.f;
    #pragma unroll
    for (int kc = 0; kc < 128; kc += 32) {
        float wr[32];
        #pragma unroll
        for (int j = 0; j < 32; ++j) wr[j] = wp[(size_t)(kc + j)*N];
        #pragma unroll
        for (int j = 0; j < 32; j += 4) {
            #pragma unroll
            for (int r = 0; r < RPT; ++r) {
                float4 v = *(const float4*)(xb + r*132 + kc + j);
                acc[r] = fmaf(v.x, wr[j+0], acc[r]);
                acc[r] = fmaf(v.y, wr[j+1], acc[r]);
                acc[r] = fmaf(v.z, wr[j+2], acc[r]);
                acc[r] = fmaf(v.w, wr[j+3], acc[r]);
            }
        }
    }
    float b = bias ? bias[c] : 0.f;
    #pragma unroll
    for (int j = 0; j < RPT; ++j) {
        float a = acc[j] + b;
        if (relu) a = fmaxf(a, 0.f);
        Y[(size_t)(row0 + g*RPT + j)*ldy + col0 + c] = a;
    }
    __syncthreads();
}

// ---------------- attention tile: (b, h, 4-query block) ----------------------
__device__ void attn_tile(
    const float* __restrict__ qkv, float* __restrict__ attout,
    int b, int h, int qb, float* __restrict__ sm)
{
    float* ksh = sm;               // 128*33 = 4224
    float* vsh = sm + 4224;        // 128*33
    float* qsh = sm + 8448;        // 4*32 = 128
    float* psh = sm + 8576;        // 4*128 = 512
    const int tid = threadIdx.x;
    #pragma unroll
    for (int i = 0; i < 4; ++i) {
        int idx = tid + i*NT;       // 0..1023 = 128 rows x 8 float4
        int j = idx >> 3, d4 = (idx & 7) * 4;
        const float* base = qkv + (size_t)(b*BBS + j)*384 + h*DK + d4;
        float4 kk = *(const float4*)(base + 128);
        float4 vv = *(const float4*)(base + 256);
        float* kd = ksh + j*33 + d4;
        kd[0] = kk.x; kd[1] = kk.y; kd[2] = kk.z; kd[3] = kk.w;
        float* vd = vsh + j*33 + d4;
        vd[0] = vv.x; vd[1] = vv.y; vd[2] = vv.z; vd[3] = vv.w;
    }
    if (tid < 128) {
        int qi = tid >> 5, d = tid & 31;
        qsh[tid] = qkv[(size_t)(b*BBS + qb*4 + qi)*384 + h*DK + d];
    }
    __syncthreads();
    const int wid = tid >> 5, lane = tid & 31;
    if (wid < 4) {
        const int q = qb*4 + wid;
        float qr[32];
        #pragma unroll
        for (int d = 0; d < 32; d += 4) {
            float4 t = *(const float4*)(qsh + wid*32 + d);
            qr[d] = t.x; qr[d+1] = t.y; qr[d+2] = t.z; qr[d+3] = t.w;
        }
        const float* k0 = ksh + (lane     )*33;
        const float* k1 = ksh + (lane + 32)*33;
        const float* k2 = ksh + (lane + 64)*33;
        const float* k3 = ksh + (lane + 96)*33;
        float s0 = 0.f, s1 = 0.f, s2 = 0.f, s3 = 0.f;
        #pragma unroll
        for (int d = 0; d < 32; ++d) {
            float qd = qr[d];
            s0 = fmaf(qd, k0[d], s0);
            s1 = fmaf(qd, k1[d], s1);
            s2 = fmaf(qd, k2[d], s2);
            s3 = fmaf(qd, k3[d], s3);
        }
        const float scale = 0.17677669529663687f;  // 1/sqrt(32)
        s0 *= scale; s1 *= scale; s2 *= scale; s3 *= scale;
        float m = fmaxf(fmaxf(s0, s1), fmaxf(s2, s3));
        #pragma unroll
        for (int o = 16; o; o >>= 1) m = fmaxf(m, __shfl_xor_sync(0xffffffffu, m, o));
        float p0 = __expf(s0 - m), p1 = __expf(s1 - m), p2 = __expf(s2 - m), p3 = __expf(s3 - m);
        float lsum = p0 + p1 + p2 + p3;
        #pragma unroll
        for (int o = 16; o; o >>= 1) lsum += __shfl_xor_sync(0xffffffffu, lsum, o);
        float* pp = psh + wid*128;
        pp[lane     ] = p0;
        pp[lane + 32] = p1;
        pp[lane + 64] = p2;
        pp[lane + 96] = p3;
        __syncwarp();
        float o0 = 0.f, o1 = 0.f, o2 = 0.f, o3 = 0.f;
        #pragma unroll 8
        for (int j = 0; j < 128; j += 4) {
            o0 = fmaf(pp[j+0], vsh[(j+0)*33 + lane], o0);
            o1 = fmaf(pp[j+1], vsh[(j+1)*33 + lane], o1);
            o2 = fmaf(pp[j+2], vsh[(j+2)*33 + lane], o2);
            o3 = fmaf(pp[j+3], vsh[(j+3)*33 + lane], o3);
        }
        attout[(size_t)(b*BBS + q)*DD + h*DK + lane] = ((o0 + o1) + (o2 + o3)) / lsum;
    }
    __syncthreads();
}

// ---------------- O-proj + residual + LN1 (4 rows/block, 64 blocks) ----------
__device__ void oproj_ln(
    const float* __restrict__ att, const float* __restrict__ W,  // k-major
    const float* __restrict__ bo, const float* __restrict__ g1,
    const float* __restrict__ be1, float* __restrict__ x,
    float* __restrict__ sm)
{
    const int row0 = blockIdx.x * 4;
    float* as   = sm;          // 4*132
    float* vals = sm + 544;    // 4*132
    float* st   = sm + 1088;   // 8
    const int tid = threadIdx.x;
    if (tid < 128) {            // 4 rows x 32 float4
        int r = tid >> 5, k4 = (tid & 31) * 4;
        float4 v = lmul_f4(*(const float4*)(att + (row0 + r)*DD + k4));
        *(float4*)(as + r*132 + k4) = v;
    }
    __syncthreads();
    const int c = tid & 127, rg = tid >> 7;       // rows rg*2, rg*2+1
    const float* x0p = as + (rg*2    )*132;
    const float* x1p = as + (rg*2 + 1)*132;
    const float* wp = W + c;
    float a0 = 0.f, a1 = 0.f;
    #pragma unroll
    for (int kc = 0; kc < 128; kc += 32) {
        float wr[32];
        #pragma unroll
        for (int j = 0; j < 32; ++j) wr[j] = wp[(kc + j)*DD];
        #pragma unroll
        for (int j = 0; j < 32; j += 4) {
            float4 v0 = *(const float4*)(x0p + kc + j);
            float4 v1 = *(const float4*)(x1p + kc + j);
            a0 = fmaf(v0.x, wr[j+0], a0); a1 = fmaf(v1.x, wr[j+0], a1);
            a0 = fmaf(v0.y, wr[j+1], a0); a1 = fmaf(v1.y, wr[j+1], a1);
            a0 = fmaf(v0.z, wr[j+2], a0); a1 = fmaf(v1.z, wr[j+2], a1);
            a0 = fmaf(v0.w, wr[j+3], a0); a1 = fmaf(v1.w, wr[j+3], a1);
        }
    }
    float b = bo[c];
    const int r0 = row0 + rg*2, r1 = r0 + 1;
    float v0 = x[r0*DD + c] + a0 + b;
    float v1 = x[r1*DD + c] + a1 + b;
    vals[(rg*2    )*132 + c] = v0;
    vals[(rg*2 + 1)*132 + c] = v1;
    __syncthreads();
    const int wid = tid >> 5, lane = tid & 31;
    if (wid < 4) {
        float s = 0.f, sq = 0.f;
        #pragma unroll
        for (int i = 0; i < 4; ++i) {
            float v = vals[wid*132 + lane + i*32];
            s += v; sq = fmaf(v, v, sq);
        }
        #pragma unroll
        for (int o = 16; o; o >>= 1) {
            s  += __shfl_xor_sync(0xffffffffu, s, o);
            sq += __shfl_xor_sync(0xffffffffu, sq, o);
        }
        if (lane == 0) {
            float mean = s * (1.f/128.f);
            float var  = sq * (1.f/128.f) - mean*mean;
            st[wid*2]     = mean;
            st[wid*2 + 1] = rsqrtf(var + 1e-5f);
        }
    }
    __syncthreads();
    {
        float gm = g1[c], bb = be1[c];
        float m0 = st[(rg*2)*2],     rs0 = st[(rg*2)*2 + 1];
        float m1 = st[(rg*2+1)*2],   rs1 = st[(rg*2+1)*2 + 1];
        x[r0*DD + c] = (v0 - m0)*rs0*gm + bb;
        x[r1*DD + c] = (v1 - m1)*rs1*gm + bb;
    }
    __syncthreads();
}

// ---------------- the one persistent kernel ----------------
__global__ void __launch_bounds__(NT, 2) model_kernel(Params P) {
    __shared__ __align__(16) float sm[9216];
    const int bid = blockIdx.x;

    // P0: weight transforms + embedding
    transform_all(&P);
    gbar();

    for (int l = 0; l < LL; ++l) {
        // P1: QKV fused GEMM — 96 tiles; at l=1 the staging also applies
        //     layer-0's FF2-combine + residual + LN2 (fused, no extra phase).
        if (bid < 96) {
            int rt = bid & 15, ct = bid >> 4;     // ct 0..5
            int col0 = ct * 64;
            int seg = col0 >> 7;                  // 0..2
            const float* segb = (seg == 0 ? P.bq : seg == 1 ? P.bk : P.bv)
                                + l*DD + (col0 & 127);
            if (l == 0) {
                gemm_kM<4,0>(g_x, DD, 0, g_twqkv[l], 384, segb, 0,
                             0, 0, 0, g_qkv, 384, rt*16, col0, sm);
            } else {
                gemm_kM<4,1>(g_x, DD, 0, g_twqkv[l], 384, segb, 0,
                             P.b2, P.g2, P.be2,       // layer 0 params
                             g_qkv, 384, rt*16, col0, sm);
            }
        }
        gbar();

        // P2: attention — 256 tiles (b, h, 4-query block)
        if (bid < 256) {
            int b = bid >> 7, h = (bid >> 5) & 3, qb = bid & 31;
            attn_tile(g_qkv, g_att, b, h, qb, sm);
        }
        gbar();

        // P3: O-proj + residual + LN1 — 64 blocks
        if (bid < 64) {
            oproj_ln(g_att, g_two[l], P.bo + l*DD, P.g1 + l*DD,
                     P.be1 + l*DD, g_x, sm);
        }
        gbar();

        // P4: FF1 + relu — 128 tiles (16 rowtiles(16r) x 8 col64)
        if (bid < 128) {
            int rt = bid & 15, ct = bid >> 4;     // ct 0..7
            gemm_kM<4,0>(g_x, DD, 0, g_tw1[l], FF, P.b1 + l*FF + ct*64, 1,
                         0, 0, 0, g_ff, FF, rt*16, ct*64, sm);
        }
        gbar();

        // P5: FF2 k-split partials — 128 tiles (16 rt x 2 col64 x 4 k-chunks)
        if (bid < 128) {
            int rt = bid & 15, ct = (bid >> 4) & 1, kc = bid >> 5;
            gemm_kM<4,0>(g_ff, FF, kc*128, g_tw2[l], DD, (const float*)0, 0,
                         0, 0, 0, g_ffp[kc], DD, rt*16, ct*64, sm);
        }
        gbar();
    }

    // P7: final vocab projection — 128 tiles (8 rowtiles(32r) x 16 col64)
    //     staging applies layer-1's FF2-combine + residual + LN2 (fused).
    if (bid < 128) {
        int rt = bid & 7, ct = bid >> 3;
        gemm_kM<8,1>(g_x, DD, 0, g_twout, VV, P.bout + ct*64, 0,
                     P.b2 + DD, P.g2 + DD, P.be2 + DD,   // layer 1 params
                     P.out, VV, rt*32, ct*64, sm);
    }
}

extern "C" void kernel_launch(void* const* d_in, const int* in_sizes, int n_in,
                              void* d_out, int out_size) {
    Params P;
    P.tokens = (const int*)  d_in[0];
    P.emb    = (const float*)d_in[1];
    P.pos    = (const float*)d_in[2];
    P.Wq     = (const float*)d_in[3];
    P.bq     = (const float*)d_in[4];
    P.Wk     = (const float*)d_in[5];
    P.bk     = (const float*)d_in[6];
    P.Wv     = (const float*)d_in[7];
    P.bv     = (const float*)d_in[8];
    P.Wo     = (const float*)d_in[9];
    P.bo     = (const float*)d_in[10];
    P.W1     = (const float*)d_in[11];
    P.b1     = (const float*)d_in[12];
    P.W2     = (const float*)d_in[13];
    P.b2     = (const float*)d_in[14];
    P.g1     = (const float*)d_in[15];
    P.be1    = (const float*)d_in[16];
    P.g2     = (const float*)d_in[17];
    P.be2    = (const float*)d_in[18];
    P.Wout   = (const float*)d_in[19];
    P.bout   = (const float*)d_in[20];
    P.out    = (float*)d_out;

    model_kernel<<<NB, NT>>>(P);
}

// round 11
// speedup vs baseline: 1.4607x; 1.0061x over previous
#include <cuda_runtime.h>
#include <math.h>

#define NB 296
#define NT 256
#define NROWS 256      // B*S
#define BBS 128        // S
#define DD 128
#define FF 512
#define VV 1024
#define DK 32
#define LL 2

// ---------------- device scratch ----------------
__device__ float g_x[NROWS*DD];
__device__ float g_qkv[NROWS*384];
__device__ float g_att[NROWS*DD];
__device__ float g_ff[NROWS*FF];
__device__ float g_ffp[4][NROWS*DD];
// transformed weights, K-MAJOR: tw[k*N + n]  (coalesced over n)
__device__ float g_twqkv[LL][DD*384];
__device__ float g_two[LL][DD*DD];
__device__ float g_tw1[LL][DD*FF];
__device__ float g_tw2[LL][FF*DD];
__device__ float g_twout[DD*VV];
__device__ unsigned g_count;
__device__ unsigned g_gen;

struct Params {
    const int* tokens; const float* emb; const float* pos;
    const float* Wq; const float* bq; const float* Wk; const float* bk;
    const float* Wv; const float* bv; const float* Wo; const float* bo;
    const float* W1; const float* b1; const float* W2; const float* b2;
    const float* g1; const float* be1; const float* g2; const float* be2;
    const float* Wout; const float* bout;
    float* out;
};

// ---------------- l_mul elementwise transform (bit-twiddled) ----------------
// Reference: e = floor(log2|x|)+1; m = x*2^-e; r = round(m*8); f = r*2^(2e-3).
__device__ __forceinline__ float lmul_f(float x) {
    unsigned bits = __float_as_uint(x);
    int expo = (int)((bits >> 23) & 0xffu);
    if (expo == 0) return 0.0f;                 // zero or denormal
    int e = expo - 126;
    if (e < -40) return 0.0f;
    float m = __int_as_float((bits & 0x807fffffu) | (126u << 23));  // x*2^-e exact
    float r = rintf(m * 8.0f);                  // round-half-even
    return r * __int_as_float((unsigned)(2*e - 3 + 127) << 23);    // exact 2^(2e-3)
}

__device__ __forceinline__ float4 lmul_f4(float4 v) {
    float4 o;
    o.x = lmul_f(v.x); o.y = lmul_f(v.y); o.z = lmul_f(v.z); o.w = lmul_f(v.w);
    return o;
}

// ---------------- grid barrier ----------------
__device__ __forceinline__ void gbar() {
    __syncthreads();
    if (threadIdx.x == 0) {
        __threadfence();
        unsigned gen = *((volatile unsigned*)&g_gen);
        if (atomicAdd(&g_count, 1u) == NB - 1u) {
            atomicExch(&g_count, 0u);
            __threadfence();
            atomicExch(&g_gen, gen + 1u);
        } else {
            while (*((volatile unsigned*)&g_gen) == gen) __nanosleep(20);
        }
        __threadfence();
    }
    __syncthreads();
}

// ---------------- phase 0: weight transform (to k-major) + embed ------------
__device__ void transform_all(const Params* __restrict__ P) {
    const int t0 = blockIdx.x * NT + threadIdx.x;
    const int STEP = NB * NT;
    for (int i = t0; i < LL*DD*384; i += STEP) {
        int l = i / (DD*384); int r = i - l*(DD*384);
        int k = r / 384, n = r - k*384;
        const float* src; int nn;
        if (n < 128)      { src = P->Wq + l*DD*DD; nn = n; }
        else if (n < 256) { src = P->Wk + l*DD*DD; nn = n - 128; }
        else              { src = P->Wv + l*DD*DD; nn = n - 256; }
        g_twqkv[l][k*384 + n] = lmul_f(src[nn*DD + k]);
    }
    for (int i = t0; i < LL*DD*DD; i += STEP) {
        int l = i / (DD*DD); int r = i - l*(DD*DD);
        int k = r >> 7, n = r & 127;
        g_two[l][k*DD + n] = lmul_f(P->Wo[l*DD*DD + n*DD + k]);
    }
    for (int i = t0; i < LL*DD*FF; i += STEP) {
        int l = i / (DD*FF); int r = i - l*(DD*FF);
        int k = r >> 9, n = r & 511;
        g_tw1[l][k*FF + n] = lmul_f(P->W1[l*FF*DD + n*DD + k]);
    }
    for (int i = t0; i < LL*FF*DD; i += STEP) {
        int l = i / (FF*DD); int r = i - l*(FF*DD);
        int k = r >> 7, n = r & 127;
        g_tw2[l][k*DD + n] = lmul_f(P->W2[l*DD*FF + n*FF + k]);
    }
    for (int i = t0; i < DD*VV; i += STEP) {
        int k = i >> 10, n = i & 1023;
        g_twout[k*VV + n] = lmul_f(P->Wout[n*DD + k]);
    }
    for (int i = t0; i < NROWS*DD; i += STEP) {
        int row = i >> 7, d = i & 127;
        int s = row & (BBS - 1);
        g_x[i] = P->emb[P->tokens[row]*DD + d] + P->pos[s*DD + d];
    }
}

// ---------------- GEMM tile: (RPT*4) rows x 64 cols, K-chunk = 128 -----------
// Weight tile goes through SMEM: cooperative coalesced float4 load (8 LDG.128
// per thread), then conflict-free stride-1 scalar LDS in the FMA loop.
// MODE 0: stage f(X rows) plainly.
// MODE 1: rows = g_x + b2 + sum(g_ffp) -> LN2 (warp-local) -> write g_x
//         (identical across col-tiles) and stage f(LN2 row).
template<int RPT, int MODE>
__device__ __forceinline__ void gemm_sw(
    const float* __restrict__ X, int ldx, int kbeg,
    const float* __restrict__ W, int N,
    const float* __restrict__ bias, int relu,
    const float* __restrict__ b2, const float* __restrict__ g2,
    const float* __restrict__ be2,
    float* __restrict__ Y, int ldy,
    int row0, int col0,
    float* __restrict__ ws /* 128*64 */, float* __restrict__ xs /* (RPT*4)*132 */)
{
    const int ROWS = RPT * 4;
    const int tid = threadIdx.x;
    const int lane = tid & 31;
    // cooperative weight tile load: 128 k x 64 n, fully coalesced
    #pragma unroll
    for (int i = 0; i < 8; ++i) {
        int idx = tid + i*NT;                // 0..2047
        int k = idx >> 4, c4 = (idx & 15) << 2;
        *(float4*)(ws + k*64 + c4) =
            *(const float4*)(W + (size_t)(kbeg + k)*N + col0 + c4);
    }
    // staging: one warp per row, float4 per lane
    #pragma unroll
    for (int i = 0; i < ROWS/8; ++i) {
        int r = (tid >> 5) + i*8;
        int k4 = lane * 4;
        if (MODE == 0) {
            float4 v = lmul_f4(*(const float4*)(X + (size_t)(row0 + r)*ldx + kbeg + k4));
            *(float4*)(xs + r*132 + k4) = v;
        } else {
            const int grow = row0 + r;
            float4 u = *(const float4*)(g_x + grow*DD + k4);
            float4 bb = *(const float4*)(b2 + k4);
            u.x += bb.x; u.y += bb.y; u.z += bb.z; u.w += bb.w;
            #pragma unroll
            for (int ks = 0; ks < 4; ++ks) {
                float4 p = *(const float4*)(g_ffp[ks] + grow*DD + k4);
                u.x += p.x; u.y += p.y; u.z += p.z; u.w += p.w;
            }
            float s  = (u.x + u.y) + (u.z + u.w);
            float sq = fmaf(u.x, u.x, fmaf(u.y, u.y, fmaf(u.z, u.z, u.w*u.w)));
            #pragma unroll
            for (int o = 16; o; o >>= 1) {
                s  += __shfl_xor_sync(0xffffffffu, s, o);
                sq += __shfl_xor_sync(0xffffffffu, sq, o);
            }
            float mean = s * (1.f/128.f);
            float rs = rsqrtf(sq * (1.f/128.f) - mean*mean + 1e-5f);
            float4 gv  = *(const float4*)(g2 + k4);
            float4 bev = *(const float4*)(be2 + k4);
            float4 ln;
            ln.x = (u.x - mean)*rs*gv.x + bev.x;
            ln.y = (u.y - mean)*rs*gv.y + bev.y;
            ln.z = (u.z - mean)*rs*gv.z + bev.z;
            ln.w = (u.w - mean)*rs*gv.w + bev.w;
            *(float4*)(g_x + grow*DD + k4) = ln;      // identical across col-tiles
            *(float4*)(xs + r*132 + k4) = lmul_f4(ln);
        }
    }
    __syncthreads();
    const int c = tid & 63;
    const int g = tid >> 6;
    const float* xb = xs + g*RPT*132;
    const float* wc = ws + c;
    float acc[RPT];
    #pragma unroll
    for (int j = 0; j < RPT; ++j) acc[j] = 0.f;
    #pragma unroll 8
    for (int k = 0; k < 128; k += 4) {
        float w0 = wc[(k+0)*64];
        float w1 = wc[(k+1)*64];
        float w2 = wc[(k+2)*64];
        float w3 = wc[(k+3)*64];
        #pragma unroll
        for (int r = 0; r < RPT; ++r) {
            float4 v = *(const float4*)(xb + r*132 + k);
            acc[r] = fmaf(v.x, w0, acc[r]);
            acc[r] = fmaf(v.y, w1, acc[r]);
            acc[r] = fmaf(v.z, w2, acc[r]);
            acc[r] = fmaf(v.w, w3, acc[r]);
        }
    }
    float b = bias ? bias[c] : 0.f;
    #pragma unroll
    for (int j = 0; j < RPT; ++j) {
        float a = acc[j] + b;
        if (relu) a = fmaxf(a, 0.f);
        Y[(size_t)(row0 + g*RPT + j)*ldy + col0 + c] = a;
    }
    __syncthreads();
}

// ---------------- attention tile: (b, h, 4-query block) ----------------------
__device__ void attn_tile(
    const float* __restrict__ qkv, float* __restrict__ attout,
    int b, int h, int qb, float* __restrict__ sm)
{
    float* ksh = sm;               // 128*33 = 4224
    float* vsh = sm + 4224;        // 128*33
    float* qsh = sm + 8448;        // 4*32 = 128
    float* psh = sm + 8576;        // 4*128 = 512
    const int tid = threadIdx.x;
    #pragma unroll
    for (int i = 0; i < 4; ++i) {
        int idx = tid + i*NT;       // 0..1023 = 128 rows x 8 float4
        int j = idx >> 3, d4 = (idx & 7) * 4;
        const float* base = qkv + (size_t)(b*BBS + j)*384 + h*DK + d4;
        float4 kk = *(const float4*)(base + 128);
        float4 vv = *(const float4*)(base + 256);
        float* kd = ksh + j*33 + d4;
        kd[0] = kk.x; kd[1] = kk.y; kd[2] = kk.z; kd[3] = kk.w;
        float* vd = vsh + j*33 + d4;
        vd[0] = vv.x; vd[1] = vv.y; vd[2] = vv.z; vd[3] = vv.w;
    }
    if (tid < 128) {
        int qi = tid >> 5, d = tid & 31;
        qsh[tid] = qkv[(size_t)(b*BBS + qb*4 + qi)*384 + h*DK + d];
    }
    __syncthreads();
    const int wid = tid >> 5, lane = tid & 31;
    if (wid < 4) {
        const int q = qb*4 + wid;
        float qr[32];
        #pragma unroll
        for (int d = 0; d < 32; d += 4) {
            float4 t = *(const float4*)(qsh + wid*32 + d);
            qr[d] = t.x; qr[d+1] = t.y; qr[d+2] = t.z; qr[d+3] = t.w;
        }
        const float* k0 = ksh + (lane     )*33;
        const float* k1 = ksh + (lane + 32)*33;
        const float* k2 = ksh + (lane + 64)*33;
        const float* k3 = ksh + (lane + 96)*33;
        float s0 = 0.f, s1 = 0.f, s2 = 0.f, s3 = 0.f;
        #pragma unroll
        for (int d = 0; d < 32; ++d) {
            float qd = qr[d];
            s0 = fmaf(qd, k0[d], s0);
            s1 = fmaf(qd, k1[d], s1);
            s2 = fmaf(qd, k2[d], s2);
            s3 = fmaf(qd, k3[d], s3);
        }
        const float scale = 0.17677669529663687f;  // 1/sqrt(32)
        s0 *= scale; s1 *= scale; s2 *= scale; s3 *= scale;
        float m = fmaxf(fmaxf(s0, s1), fmaxf(s2, s3));
        #pragma unroll
        for (int o = 16; o; o >>= 1) m = fmaxf(m, __shfl_xor_sync(0xffffffffu, m, o));
        float p0 = __expf(s0 - m), p1 = __expf(s1 - m), p2 = __expf(s2 - m), p3 = __expf(s3 - m);
        float lsum = p0 + p1 + p2 + p3;
        #pragma unroll
        for (int o = 16; o; o >>= 1) lsum += __shfl_xor_sync(0xffffffffu, lsum, o);
        float* pp = psh + wid*128;
        pp[lane     ] = p0;
        pp[lane + 32] = p1;
        pp[lane + 64] = p2;
        pp[lane + 96] = p3;
        __syncwarp();
        float o0 = 0.f, o1 = 0.f, o2 = 0.f, o3 = 0.f;
        #pragma unroll 8
        for (int j = 0; j < 128; j += 4) {
            o0 = fmaf(pp[j+0], vsh[(j+0)*33 + lane], o0);
            o1 = fmaf(pp[j+1], vsh[(j+1)*33 + lane], o1);
            o2 = fmaf(pp[j+2], vsh[(j+2)*33 + lane], o2);
            o3 = fmaf(pp[j+3], vsh[(j+3)*33 + lane], o3);
        }
        attout[(size_t)(b*BBS + q)*DD + h*DK + lane] = ((o0 + o1) + (o2 + o3)) / lsum;
    }
    __syncthreads();
}

// ---------------- O-proj + residual + LN1 (4 rows/block, 64 blocks) ----------
__device__ void oproj_ln(
    const float* __restrict__ att, const float* __restrict__ W,  // k-major
    const float* __restrict__ bo, const float* __restrict__ g1,
    const float* __restrict__ be1, float* __restrict__ x,
    float* __restrict__ sm)
{
    const int row0 = blockIdx.x * 4;
    float* as   = sm;          // 4*132
    float* vals = sm + 544;    // 4*132
    float* st   = sm + 1088;   // 8
    const int tid = threadIdx.x;
    if (tid < 128) {            // 4 rows x 32 float4
        int r = tid >> 5, k4 = (tid & 31) * 4;
        float4 v = lmul_f4(*(const float4*)(att + (row0 + r)*DD + k4));
        *(float4*)(as + r*132 + k4) = v;
    }
    __syncthreads();
    const int c = tid & 127, rg = tid >> 7;       // rows rg*2, rg*2+1
    const float* x0p = as + (rg*2    )*132;
    const float* x1p = as + (rg*2 + 1)*132;
    const float* wp = W + c;
    float a0 = 0.f, a1 = 0.f;
    #pragma unroll
    for (int kc = 0; kc < 128; kc += 32) {
        float wr[32];
        #pragma unroll
        for (int j = 0; j < 32; ++j) wr[j] = wp[(kc + j)*DD];
        #pragma unroll
        for (int j = 0; j < 32; j += 4) {
            float4 v0 = *(const float4*)(x0p + kc + j);
            float4 v1 = *(const float4*)(x1p + kc + j);
            a0 = fmaf(v0.x, wr[j+0], a0); a1 = fmaf(v1.x, wr[j+0], a1);
            a0 = fmaf(v0.y, wr[j+1], a0); a1 = fmaf(v1.y, wr[j+1], a1);
            a0 = fmaf(v0.z, wr[j+2], a0); a1 = fmaf(v1.z, wr[j+2], a1);
            a0 = fmaf(v0.w, wr[j+3], a0); a1 = fmaf(v1.w, wr[j+3], a1);
        }
    }
    float b = bo[c];
    const int r0 = row0 + rg*2, r1 = r0 + 1;
    float v0 = x[r0*DD + c] + a0 + b;
    float v1 = x[r1*DD + c] + a1 + b;
    vals[(rg*2    )*132 + c] = v0;
    vals[(rg*2 + 1)*132 + c] = v1;
    __syncthreads();
    const int wid = tid >> 5, lane = tid & 31;
    if (wid < 4) {
        float s = 0.f, sq = 0.f;
        #pragma unroll
        for (int i = 0; i < 4; ++i) {
            float v = vals[wid*132 + lane + i*32];
            s += v; sq = fmaf(v, v, sq);
        }
        #pragma unroll
        for (int o = 16; o; o >>= 1) {
            s  += __shfl_xor_sync(0xffffffffu, s, o);
            sq += __shfl_xor_sync(0xffffffffu, sq, o);
        }
        if (lane == 0) {
            float mean = s * (1.f/128.f);
            float var  = sq * (1.f/128.f) - mean*mean;
            st[wid*2]     = mean;
            st[wid*2 + 1] = rsqrtf(var + 1e-5f);
        }
    }
    __syncthreads();
    {
        float gm = g1[c], bb = be1[c];
        float m0 = st[(rg*2)*2],     rs0 = st[(rg*2)*2 + 1];
        float m1 = st[(rg*2+1)*2],   rs1 = st[(rg*2+1)*2 + 1];
        x[r0*DD + c] = (v0 - m0)*rs0*gm + bb;
        x[r1*DD + c] = (v1 - m1)*rs1*gm + bb;
    }
    __syncthreads();
}

// ---------------- the one persistent kernel ----------------
__global__ void __launch_bounds__(NT, 2) model_kernel(Params P) {
    __shared__ __align__(16) float sm[10304];   // ws[8192] + xs[2112]; attn uses 9216
    float* ws = sm;
    float* xs = sm + 8192;
    const int bid = blockIdx.x;

    // P0: weight transforms + embedding
    transform_all(&P);
    gbar();

    for (int l = 0; l < LL; ++l) {
        // P1: QKV fused GEMM — 96 tiles (16 rowtiles(16r) x 6 col64);
        //     at l=1 the staging also applies layer-0 FF2+residual+LN2.
        if (bid < 96) {
            int rt = bid & 15, ct = bid >> 4;     // ct 0..5
            int col0 = ct * 64;
            int seg = col0 >> 7;                  // 0..2
            const float* segb = (seg == 0 ? P.bq : seg == 1 ? P.bk : P.bv)
                                + l*DD + (col0 & 127);
            if (l == 0) {
                gemm_sw<4,0>(g_x, DD, 0, g_twqkv[l], 384, segb, 0,
                             0, 0, 0, g_qkv, 384, rt*16, col0, ws, xs);
            } else {
                gemm_sw<4,1>(g_x, DD, 0, g_twqkv[l], 384, segb, 0,
                             P.b2, P.g2, P.be2,
                             g_qkv, 384, rt*16, col0, ws, xs);
            }
        }
        gbar();

        // P2: attention — 256 tiles (b, h, 4-query block)
        if (bid < 256) {
            int b = bid >> 7, h = (bid >> 5) & 3, qb = bid & 31;
            attn_tile(g_qkv, g_att, b, h, qb, sm);
        }
        gbar();

        // P3: O-proj + residual + LN1 — 64 blocks
        if (bid < 64) {
            oproj_ln(g_att, g_two[l], P.bo + l*DD, P.g1 + l*DD,
                     P.be1 + l*DD, g_x, sm);
        }
        gbar();

        // P4: FF1 + relu — 128 tiles (16 rowtiles(16r) x 8 col64)
        if (bid < 128) {
            int rt = bid & 15, ct = bid >> 4;     // ct 0..7
            gemm_sw<4,0>(g_x, DD, 0, g_tw1[l], FF, P.b1 + l*FF + ct*64, 1,
                         0, 0, 0, g_ff, FF, rt*16, ct*64, ws, xs);
        }
        gbar();

        // P5: FF2 k-split partials — 128 tiles (16 rt x 2 col64 x 4 k-chunks)
        if (bid < 128) {
            int rt = bid & 15, ct = (bid >> 4) & 1, kc = bid >> 5;
            gemm_sw<4,0>(g_ff, FF, kc*128, g_tw2[l], DD, (const float*)0, 0,
                         0, 0, 0, g_ffp[kc], DD, rt*16, ct*64, ws, xs);
        }
        gbar();
    }

    // P7: final vocab projection — 256 tiles (16 rowtiles(16r) x 16 col64);
    //     staging applies layer-1 FF2+residual+LN2 (fused).
    if (bid < 256) {
        int rt = bid & 15, ct = bid >> 4;
        gemm_sw<4,1>(g_x, DD, 0, g_twout, VV, P.bout + ct*64, 0,
                     P.b2 + DD, P.g2 + DD, P.be2 + DD,
                     P.out, VV, rt*16, ct*64, ws, xs);
    }
}

extern "C" void kernel_launch(void* const* d_in, const int* in_sizes, int n_in,
                              void* d_out, int out_size) {
    Params P;
    P.tokens = (const int*)  d_in[0];
    P.emb    = (const float*)d_in[1];
    P.pos    = (const float*)d_in[2];
    P.Wq     = (const float*)d_in[3];
    P.bq     = (const float*)d_in[4];
    P.Wk     = (const float*)d_in[5];
    P.bk     = (const float*)d_in[6];
    P.Wv     = (const float*)d_in[7];
    P.bv     = (const float*)d_in[8];
    P.Wo     = (const float*)d_in[9];
    P.bo     = (const float*)d_in[10];
    P.W1     = (const float*)d_in[11];
    P.b1     = (const float*)d_in[12];
    P.W2     = (const float*)d_in[13];
    P.b2     = (const float*)d_in[14];
    P.g1     = (const float*)d_in[15];
    P.be1    = (const float*)d_in[16];
    P.g2     = (const float*)d_in[17];
    P.be2    = (const float*)d_in[18];
    P.Wout   = (const float*)d_in[19];
    P.bout   = (const float*)d_in[20];
    P.out    = (float*)d_out;

    model_kernel<<<NB, NT>>>(P);
}

// round 12
// speedup vs baseline: 1.7089x; 1.1699x over previous
#include <cuda_runtime.h>
#include <math.h>

#define NB 296
#define NT 256
#define NROWS 256      // B*S
#define BBS 128        // S
#define DD 128
#define FF 512
#define VV 1024
#define DK 32
#define LL 2

// ---------------- device scratch ----------------
__device__ float g_x[NROWS*DD];
__device__ float g_qkv[NROWS*384];
__device__ float g_att[NROWS*DD];
__device__ float g_ff[NROWS*FF];
__device__ float g_ffp[4][NROWS*DD];
// transformed weights, K-MAJOR: tw[k*N + n]  (coalesced over n)
__device__ float g_twqkv[LL][DD*384];
__device__ float g_two[LL][DD*DD];
__device__ float g_tw1[LL][DD*FF];
__device__ float g_tw2[LL][FF*DD];
__device__ float g_twout[DD*VV];
__device__ unsigned g_count;
__device__ unsigned g_gen;

struct Params {
    const int* tokens; const float* emb; const float* pos;
    const float* Wq; const float* bq; const float* Wk; const float* bk;
    const float* Wv; const float* bv; const float* Wo; const float* bo;
    const float* W1; const float* b1; const float* W2; const float* b2;
    const float* g1; const float* be1; const float* g2; const float* be2;
    const float* Wout; const float* bout;
    float* out;
};

// ---------------- l_mul elementwise transform (bit-twiddled) ----------------
// Reference: e = floor(log2|x|)+1; m = x*2^-e; r = round(m*8); f = r*2^(2e-3).
// f values are integers r (|r|<=8) times powers of two: exactly representable
// in tf32 (10 mantissa bits) -> tensor-core products are bit-exact.
__device__ __forceinline__ float lmul_f(float x) {
    unsigned bits = __float_as_uint(x);
    int expo = (int)((bits >> 23) & 0xffu);
    if (expo == 0) return 0.0f;                 // zero or denormal
    int e = expo - 126;
    if (e < -40) return 0.0f;
    float m = __int_as_float((bits & 0x807fffffu) | (126u << 23));  // x*2^-e exact
    float r = rintf(m * 8.0f);                  // round-half-even
    return r * __int_as_float((unsigned)(2*e - 3 + 127) << 23);    // exact 2^(2e-3)
}

__device__ __forceinline__ float4 lmul_f4(float4 v) {
    float4 o;
    o.x = lmul_f(v.x); o.y = lmul_f(v.y); o.z = lmul_f(v.z); o.w = lmul_f(v.w);
    return o;
}

// ---------------- grid barrier ----------------
__device__ __forceinline__ void gbar() {
    __syncthreads();
    if (threadIdx.x == 0) {
        __threadfence();
        unsigned gen = *((volatile unsigned*)&g_gen);
        if (atomicAdd(&g_count, 1u) == NB - 1u) {
            atomicExch(&g_count, 0u);
            __threadfence();
            atomicExch(&g_gen, gen + 1u);
        } else {
            while (*((volatile unsigned*)&g_gen) == gen) __nanosleep(20);
        }
        __threadfence();
    }
    __syncthreads();
}

// ---------------- phase 0: weight transform (to k-major) + embed ------------
__device__ void transform_all(const Params* __restrict__ P) {
    const int t0 = blockIdx.x * NT + threadIdx.x;
    const int STEP = NB * NT;
    for (int i = t0; i < LL*DD*384; i += STEP) {
        int l = i / (DD*384); int r = i - l*(DD*384);
        int k = r / 384, n = r - k*384;
        const float* src; int nn;
        if (n < 128)      { src = P->Wq + l*DD*DD; nn = n; }
        else if (n < 256) { src = P->Wk + l*DD*DD; nn = n - 128; }
        else              { src = P->Wv + l*DD*DD; nn = n - 256; }
        g_twqkv[l][k*384 + n] = lmul_f(src[nn*DD + k]);
    }
    for (int i = t0; i < LL*DD*DD; i += STEP) {
        int l = i / (DD*DD); int r = i - l*(DD*DD);
        int k = r >> 7, n = r & 127;
        g_two[l][k*DD + n] = lmul_f(P->Wo[l*DD*DD + n*DD + k]);
    }
    for (int i = t0; i < LL*DD*FF; i += STEP) {
        int l = i / (DD*FF); int r = i - l*(DD*FF);
        int k = r >> 9, n = r & 511;
        g_tw1[l][k*FF + n] = lmul_f(P->W1[l*FF*DD + n*DD + k]);
    }
    for (int i = t0; i < LL*FF*DD; i += STEP) {
        int l = i / (FF*DD); int r = i - l*(FF*DD);
        int k = r >> 7, n = r & 127;
        g_tw2[l][k*DD + n] = lmul_f(P->W2[l*DD*FF + n*FF + k]);
    }
    for (int i = t0; i < DD*VV; i += STEP) {
        int k = i >> 10, n = i & 1023;
        g_twout[k*VV + n] = lmul_f(P->Wout[n*DD + k]);
    }
    for (int i = t0; i < NROWS*DD; i += STEP) {
        int row = i >> 7, d = i & 127;
        int s = row & (BBS - 1);
        g_x[i] = P->emb[P->tokens[row]*DD + d] + P->pos[s*DD + d];
    }
}

// ---------------- tensor-core GEMM tile: 16 rows x 64 cols, K = 128 ----------
// mma.sync.m16n8k4 tf32. 8 warps, each owns an 8-col strip (all 16 rows).
// ws stride 72 (B-frag conflict-free), xs stride 132 (A-frag conflict-free).
// MODE 0: stage f(X rows). MODE 1: rows = g_x + b2 + sum(g_ffp) -> LN2 ->
//         write g_x (identical across col-tiles) and stage f(LN2 row).
#define WSS 72
template<int MODE>
__device__ __forceinline__ void gemm_mma(
    const float* __restrict__ X, int ldx, int kbeg,
    const float* __restrict__ W, int N,
    const float* __restrict__ bias, int relu,
    const float* __restrict__ b2, const float* __restrict__ g2,
    const float* __restrict__ be2,
    float* __restrict__ Y, int ldy,
    int row0, int col0,
    float* __restrict__ ws /* 128*WSS */, float* __restrict__ xs /* 16*132 */)
{
    const int tid = threadIdx.x;
    const int lane = tid & 31;
    // cooperative weight tile load: 128 k x 64 n, coalesced float4
    #pragma unroll
    for (int i = 0; i < 8; ++i) {
        int idx = tid + i*NT;                // 0..2047
        int k = idx >> 4, c4 = (idx & 15) << 2;
        *(float4*)(ws + k*WSS + c4) =
            *(const float4*)(W + (size_t)(kbeg + k)*N + col0 + c4);
    }
    // staging: one warp per row, float4 per lane (16 rows)
    #pragma unroll
    for (int i = 0; i < 2; ++i) {
        int r = (tid >> 5) + i*8;
        int k4 = lane * 4;
        if (MODE == 0) {
            float4 v = lmul_f4(*(const float4*)(X + (size_t)(row0 + r)*ldx + kbeg + k4));
            *(float4*)(xs + r*132 + k4) = v;
        } else {
            const int grow = row0 + r;
            float4 u = *(const float4*)(g_x + grow*DD + k4);
            float4 bb = *(const float4*)(b2 + k4);
            u.x += bb.x; u.y += bb.y; u.z += bb.z; u.w += bb.w;
            #pragma unroll
            for (int ks = 0; ks < 4; ++ks) {
                float4 p = *(const float4*)(g_ffp[ks] + grow*DD + k4);
                u.x += p.x; u.y += p.y; u.z += p.z; u.w += p.w;
            }
            float s  = (u.x + u.y) + (u.z + u.w);
            float sq = fmaf(u.x, u.x, fmaf(u.y, u.y, fmaf(u.z, u.z, u.w*u.w)));
            #pragma unroll
            for (int o = 16; o; o >>= 1) {
                s  += __shfl_xor_sync(0xffffffffu, s, o);
                sq += __shfl_xor_sync(0xffffffffu, sq, o);
            }
            float mean = s * (1.f/128.f);
            float rs = rsqrtf(sq * (1.f/128.f) - mean*mean + 1e-5f);
            float4 gv  = *(const float4*)(g2 + k4);
            float4 bev = *(const float4*)(be2 + k4);
            float4 ln;
            ln.x = (u.x - mean)*rs*gv.x + bev.x;
            ln.y = (u.y - mean)*rs*gv.y + bev.y;
            ln.z = (u.z - mean)*rs*gv.z + bev.z;
            ln.w = (u.w - mean)*rs*gv.w + bev.w;
            *(float4*)(g_x + grow*DD + k4) = ln;      // identical across col-tiles
            *(float4*)(xs + r*132 + k4) = lmul_f4(ln);
        }
    }
    __syncthreads();

    const int w = tid >> 5;            // warp id 0..7 -> n-strip w*8
    const int g = lane >> 2;           // 0..7
    const int t = lane & 3;            // 0..3
    const float* xr0 = xs + g*132;          // A row g
    const float* xr1 = xs + (g + 8)*132;    // A row g+8
    const float* wb  = ws + w*8 + g;        // B col (local) w*8+g
    // two accumulator sets to break the HMMA RAW chain
    float c0a=0.f,c1a=0.f,c2a=0.f,c3a=0.f;
    float c0b=0.f,c1b=0.f,c2b=0.f,c3b=0.f;
    #pragma unroll
    for (int k0 = 0; k0 < 128; k0 += 8) {
        unsigned a0 = __float_as_uint(xr0[k0 + t]);
        unsigned a1 = __float_as_uint(xr1[k0 + t]);
        unsigned b0 = __float_as_uint(wb[(k0 + t)*WSS]);
        asm volatile(
            "mma.sync.aligned.m16n8k4.row.col.f32.tf32.tf32.f32 "
            "{%0,%1,%2,%3}, {%4,%5}, {%6}, {%0,%1,%2,%3};"
            : "+f"(c0a), "+f"(c1a), "+f"(c2a), "+f"(c3a)
            : "r"(a0), "r"(a1), "r"(b0));
        unsigned a2 = __float_as_uint(xr0[k0 + 4 + t]);
        unsigned a3 = __float_as_uint(xr1[k0 + 4 + t]);
        unsigned b1 = __float_as_uint(wb[(k0 + 4 + t)*WSS]);
        asm volatile(
            "mma.sync.aligned.m16n8k4.row.col.f32.tf32.tf32.f32 "
            "{%0,%1,%2,%3}, {%4,%5}, {%6}, {%0,%1,%2,%3};"
            : "+f"(c0b), "+f"(c1b), "+f"(c2b), "+f"(c3b)
            : "r"(a2), "r"(a3), "r"(b1));
    }
    float c0 = c0a + c0b, c1 = c1a + c1b, c2 = c2a + c2b, c3 = c3a + c3b;
    // epilogue: bias + relu + store (C frag: rows g / g+8, cols 2t, 2t+1)
    int cl = w*8 + 2*t;                   // local col of c0/c2
    float b0v = bias ? bias[cl]     : 0.f;
    float b1v = bias ? bias[cl + 1] : 0.f;
    c0 += b0v; c1 += b1v; c2 += b0v; c3 += b1v;
    if (relu) {
        c0 = fmaxf(c0, 0.f); c1 = fmaxf(c1, 0.f);
        c2 = fmaxf(c2, 0.f); c3 = fmaxf(c3, 0.f);
    }
    float2* y0 = (float2*)(Y + (size_t)(row0 + g    )*ldy + col0 + cl);
    float2* y1 = (float2*)(Y + (size_t)(row0 + g + 8)*ldy + col0 + cl);
    *y0 = make_float2(c0, c1);
    *y1 = make_float2(c2, c3);
    __syncthreads();
}

// ---------------- attention tile: (b, h, 4-query block) ----------------------
__device__ void attn_tile(
    const float* __restrict__ qkv, float* __restrict__ attout,
    int b, int h, int qb, float* __restrict__ sm)
{
    float* ksh = sm;               // 128*33 = 4224
    float* vsh = sm + 4224;        // 128*33
    float* qsh = sm + 8448;        // 4*32 = 128
    float* psh = sm + 8576;        // 4*128 = 512
    const int tid = threadIdx.x;
    #pragma unroll
    for (int i = 0; i < 4; ++i) {
        int idx = tid + i*NT;       // 0..1023 = 128 rows x 8 float4
        int j = idx >> 3, d4 = (idx & 7) * 4;
        const float* base = qkv + (size_t)(b*BBS + j)*384 + h*DK + d4;
        float4 kk = *(const float4*)(base + 128);
        float4 vv = *(const float4*)(base + 256);
        float* kd = ksh + j*33 + d4;
        kd[0] = kk.x; kd[1] = kk.y; kd[2] = kk.z; kd[3] = kk.w;
        float* vd = vsh + j*33 + d4;
        vd[0] = vv.x; vd[1] = vv.y; vd[2] = vv.z; vd[3] = vv.w;
    }
    if (tid < 128) {
        int qi = tid >> 5, d = tid & 31;
        qsh[tid] = qkv[(size_t)(b*BBS + qb*4 + qi)*384 + h*DK + d];
    }
    __syncthreads();
    const int wid = tid >> 5, lane = tid & 31;
    if (wid < 4) {
        const int q = qb*4 + wid;
        float qr[32];
        #pragma unroll
        for (int d = 0; d < 32; d += 4) {
            float4 t = *(const float4*)(qsh + wid*32 + d);
            qr[d] = t.x; qr[d+1] = t.y; qr[d+2] = t.z; qr[d+3] = t.w;
        }
        const float* k0 = ksh + (lane     )*33;
        const float* k1 = ksh + (lane + 32)*33;
        const float* k2 = ksh + (lane + 64)*33;
        const float* k3 = ksh + (lane + 96)*33;
        float s0 = 0.f, s1 = 0.f, s2 = 0.f, s3 = 0.f;
        #pragma unroll
        for (int d = 0; d < 32; ++d) {
            float qd = qr[d];
            s0 = fmaf(qd, k0[d], s0);
            s1 = fmaf(qd, k1[d], s1);
            s2 = fmaf(qd, k2[d], s2);
            s3 = fmaf(qd, k3[d], s3);
        }
        const float scale = 0.17677669529663687f;  // 1/sqrt(32)
        s0 *= scale; s1 *= scale; s2 *= scale; s3 *= scale;
        float m = fmaxf(fmaxf(s0, s1), fmaxf(s2, s3));
        #pragma unroll
        for (int o = 16; o; o >>= 1) m = fmaxf(m, __shfl_xor_sync(0xffffffffu, m, o));
        float p0 = __expf(s0 - m), p1 = __expf(s1 - m), p2 = __expf(s2 - m), p3 = __expf(s3 - m);
        float lsum = p0 + p1 + p2 + p3;
        #pragma unroll
        for (int o = 16; o; o >>= 1) lsum += __shfl_xor_sync(0xffffffffu, lsum, o);
        float* pp = psh + wid*128;
        pp[lane     ] = p0;
        pp[lane + 32] = p1;
        pp[lane + 64] = p2;
        pp[lane + 96] = p3;
        __syncwarp();
        float o0 = 0.f, o1 = 0.f, o2 = 0.f, o3 = 0.f;
        #pragma unroll 8
        for (int j = 0; j < 128; j += 4) {
            o0 = fmaf(pp[j+0], vsh[(j+0)*33 + lane], o0);
            o1 = fmaf(pp[j+1], vsh[(j+1)*33 + lane], o1);
            o2 = fmaf(pp[j+2], vsh[(j+2)*33 + lane], o2);
            o3 = fmaf(pp[j+3], vsh[(j+3)*33 + lane], o3);
        }
        attout[(size_t)(b*BBS + q)*DD + h*DK + lane] = ((o0 + o1) + (o2 + o3)) / lsum;
    }
    __syncthreads();
}

// ---------------- O-proj + residual + LN1 (4 rows/block, 64 blocks) ----------
__device__ void oproj_ln(
    const float* __restrict__ att, const float* __restrict__ W,  // k-major
    const float* __restrict__ bo, const float* __restrict__ g1,
    const float* __restrict__ be1, float* __restrict__ x,
    float* __restrict__ sm)
{
    const int row0 = blockIdx.x * 4;
    float* as   = sm;          // 4*132
    float* vals = sm + 544;    // 4*132
    float* st   = sm + 1088;   // 8
    const int tid = threadIdx.x;
    if (tid < 128) {            // 4 rows x 32 float4
        int r = tid >> 5, k4 = (tid & 31) * 4;
        float4 v = lmul_f4(*(const float4*)(att + (row0 + r)*DD + k4));
        *(float4*)(as + r*132 + k4) = v;
    }
    __syncthreads();
    const int c = tid & 127, rg = tid >> 7;       // rows rg*2, rg*2+1
    const float* x0p = as + (rg*2    )*132;
    const float* x1p = as + (rg*2 + 1)*132;
    const float* wp = W + c;
    float a0 = 0.f, a1 = 0.f;
    #pragma unroll
    for (int kc = 0; kc < 128; kc += 32) {
        float wr[32];
        #pragma unroll
        for (int j = 0; j < 32; ++j) wr[j] = wp[(kc + j)*DD];
        #pragma unroll
        for (int j = 0; j < 32; j += 4) {
            float4 v0 = *(const float4*)(x0p + kc + j);
            float4 v1 = *(const float4*)(x1p + kc + j);
            a0 = fmaf(v0.x, wr[j+0], a0); a1 = fmaf(v1.x, wr[j+0], a1);
            a0 = fmaf(v0.y, wr[j+1], a0); a1 = fmaf(v1.y, wr[j+1], a1);
            a0 = fmaf(v0.z, wr[j+2], a0); a1 = fmaf(v1.z, wr[j+2], a1);
            a0 = fmaf(v0.w, wr[j+3], a0); a1 = fmaf(v1.w, wr[j+3], a1);
        }
    }
    float b = bo[c];
    const int r0 = row0 + rg*2, r1 = r0 + 1;
    float v0 = x[r0*DD + c] + a0 + b;
    float v1 = x[r1*DD + c] + a1 + b;
    vals[(rg*2    )*132 + c] = v0;
    vals[(rg*2 + 1)*132 + c] = v1;
    __syncthreads();
    const int wid = tid >> 5, lane = tid & 31;
    if (wid < 4) {
        float s = 0.f, sq = 0.f;
        #pragma unroll
        for (int i = 0; i < 4; ++i) {
            float v = vals[wid*132 + lane + i*32];
            s += v; sq = fmaf(v, v, sq);
        }
        #pragma unroll
        for (int o = 16; o; o >>= 1) {
            s  += __shfl_xor_sync(0xffffffffu, s, o);
            sq += __shfl_xor_sync(0xffffffffu, sq, o);
        }
        if (lane == 0) {
            float mean = s * (1.f/128.f);
            float var  = sq * (1.f/128.f) - mean*mean;
            st[wid*2]     = mean;
            st[wid*2 + 1] = rsqrtf(var + 1e-5f);
        }
    }
    __syncthreads();
    {
        float gm = g1[c], bb = be1[c];
        float m0 = st[(rg*2)*2],     rs0 = st[(rg*2)*2 + 1];
        float m1 = st[(rg*2+1)*2],   rs1 = st[(rg*2+1)*2 + 1];
        x[r0*DD + c] = (v0 - m0)*rs0*gm + bb;
        x[r1*DD + c] = (v1 - m1)*rs1*gm + bb;
    }
    __syncthreads();
}

// ---------------- the one persistent kernel ----------------
__global__ void __launch_bounds__(NT, 2) model_kernel(Params P) {
    __shared__ __align__(16) float sm[128*WSS + 16*132];   // 45.3KB
    float* ws = sm;
    float* xs = sm + 128*WSS;
    const int bid = blockIdx.x;

    // P0: weight transforms + embedding
    transform_all(&P);
    gbar();

    for (int l = 0; l < LL; ++l) {
        // P1: QKV fused GEMM — 96 tiles (16 rowtiles(16r) x 6 col64);
        //     at l=1 staging also applies layer-0 FF2+residual+LN2.
        if (bid < 96) {
            int rt = bid & 15, ct = bid >> 4;     // ct 0..5
            int col0 = ct * 64;
            int seg = col0 >> 7;                  // 0..2
            const float* segb = (seg == 0 ? P.bq : seg == 1 ? P.bk : P.bv)
                                + l*DD + (col0 & 127);
            if (l == 0) {
                gemm_mma<0>(g_x, DD, 0, g_twqkv[l], 384, segb, 0,
                            0, 0, 0, g_qkv, 384, rt*16, col0, ws, xs);
            } else {
                gemm_mma<1>(g_x, DD, 0, g_twqkv[l], 384, segb, 0,
                            P.b2, P.g2, P.be2,
                            g_qkv, 384, rt*16, col0, ws, xs);
            }
        }
        gbar();

        // P2: attention — 256 tiles (b, h, 4-query block)
        if (bid < 256) {
            int b = bid >> 7, h = (bid >> 5) & 3, qb = bid & 31;
            attn_tile(g_qkv, g_att, b, h, qb, sm);
        }
        gbar();

        // P3: O-proj + residual + LN1 — 64 blocks
        if (bid < 64) {
            oproj_ln(g_att, g_two[l], P.bo + l*DD, P.g1 + l*DD,
                     P.be1 + l*DD, g_x, sm);
        }
        gbar();

        // P4: FF1 + relu — 128 tiles (16 rowtiles(16r) x 8 col64)
        if (bid < 128) {
            int rt = bid & 15, ct = bid >> 4;     // ct 0..7
            gemm_mma<0>(g_x, DD, 0, g_tw1[l], FF, P.b1 + l*FF + ct*64, 1,
                        0, 0, 0, g_ff, FF, rt*16, ct*64, ws, xs);
        }
        gbar();

        // P5: FF2 k-split partials — 128 tiles (16 rt x 2 col64 x 4 k-chunks)
        if (bid < 128) {
            int rt = bid & 15, ct = (bid >> 4) & 1, kc = bid >> 5;
            gemm_mma<0>(g_ff, FF, kc*128, g_tw2[l], DD, (const float*)0, 0,
                        0, 0, 0, g_ffp[kc], DD, rt*16, ct*64, ws, xs);
        }
        gbar();
    }

    // P7: final vocab projection — 256 tiles (16 rowtiles(16r) x 16 col64);
    //     staging applies layer-1 FF2+residual+LN2 (fused).
    if (bid < 256) {
        int rt = bid & 15, ct = bid >> 4;
        gemm_mma<1>(g_x, DD, 0, g_twout, VV, P.bout + ct*64, 0,
                    P.b2 + DD, P.g2 + DD, P.be2 + DD,
                    P.out, VV, rt*16, ct*64, ws, xs);
    }
}

extern "C" void kernel_launch(void* const* d_in, const int* in_sizes, int n_in,
                              void* d_out, int out_size) {
    Params P;
    P.tokens = (const int*)  d_in[0];
    P.emb    = (const float*)d_in[1];
    P.pos    = (const float*)d_in[2];
    P.Wq     = (const float*)d_in[3];
    P.bq     = (const float*)d_in[4];
    P.Wk     = (const float*)d_in[5];
    P.bk     = (const float*)d_in[6];
    P.Wv     = (const float*)d_in[7];
    P.bv     = (const float*)d_in[8];
    P.Wo     = (const float*)d_in[9];
    P.bo     = (const float*)d_in[10];
    P.W1     = (const float*)d_in[11];
    P.b1     = (const float*)d_in[12];
    P.W2     = (const float*)d_in[13];
    P.b2     = (const float*)d_in[14];
    P.g1     = (const float*)d_in[15];
    P.be1    = (const float*)d_in[16];
    P.g2     = (const float*)d_in[17];
    P.be2    = (const float*)d_in[18];
    P.Wout   = (const float*)d_in[19];
    P.bout   = (const float*)d_in[20];
    P.out    = (float*)d_out;

    model_kernel<<<NB, NT>>>(P);
}

// round 14
// speedup vs baseline: 1.8348x; 1.0737x over previous
#include <cuda_runtime.h>
#include <math.h>

#define NB 296
#define NT 256
#define NROWS 256      // B*S
#define BBS 128        // S
#define DD 128
#define FF 512
#define VV 1024
#define DK 32
#define LL 2

// ---------------- device scratch ----------------
__device__ float g_x[NROWS*DD];
__device__ float g_qkv[NROWS*384];
__device__ float g_ff[NROWS*FF];
__device__ float g_ffp[4][NROWS*DD];   // head-partials (attn) / k-split partials (FF2)
// transformed weights, K-MAJOR: tw[k*N + n]
__device__ float g_twqkv[LL][DD*384];
__device__ float g_two[LL][DD*DD];
__device__ float g_tw1[LL][DD*FF];
__device__ float g_tw2[LL][FF*DD];
__device__ float g_twout[DD*VV];
__device__ unsigned g_count;
__device__ unsigned g_gen;

struct Params {
    const int* tokens; const float* emb; const float* pos;
    const float* Wq; const float* bq; const float* Wk; const float* bk;
    const float* Wv; const float* bv; const float* Wo; const float* bo;
    const float* W1; const float* b1; const float* W2; const float* b2;
    const float* g1; const float* be1; const float* g2; const float* be2;
    const float* Wout; const float* bout;
    float* out;
};

// ---------------- l_mul elementwise transform (bit-twiddled) ----------------
// f(x) = round(x*2^-e * 8) * 2^(2e-3), e = rawexp-126. Exact in tf32.
__device__ __forceinline__ float lmul_f(float x) {
    unsigned bits = __float_as_uint(x);
    int expo = (int)((bits >> 23) & 0xffu);
    if (expo == 0) return 0.0f;
    int e = expo - 126;
    if (e < -40) return 0.0f;
    float m = __int_as_float((bits & 0x807fffffu) | (126u << 23));
    float r = rintf(m * 8.0f);
    return r * __int_as_float((unsigned)(2*e - 3 + 127) << 23);
}

__device__ __forceinline__ float4 lmul_f4(float4 v) {
    float4 o;
    o.x = lmul_f(v.x); o.y = lmul_f(v.y); o.z = lmul_f(v.z); o.w = lmul_f(v.w);
    return o;
}

// ---------------- grid barrier ----------------
__device__ __forceinline__ void gbar() {
    __syncthreads();
    if (threadIdx.x == 0) {
        __threadfence();
        unsigned gen = *((volatile unsigned*)&g_gen);
        if (atomicAdd(&g_count, 1u) == NB - 1u) {
            atomicExch(&g_count, 0u);
            __threadfence();
            atomicExch(&g_gen, gen + 1u);
        } else {
            while (*((volatile unsigned*)&g_gen) == gen) __nanosleep(20);
        }
        __threadfence();
    }
    __syncthreads();
}

// ---------------- transform helper: coalesced reads, scattered writes --------
// src row-major [n*K + k] -> dst[k*N + segoff + n]
template<int K>
__device__ __forceinline__ void xf(const float* __restrict__ src,
                                   float* __restrict__ dst,
                                   int N, int segoff, int nElem,
                                   int i0, int step) {
    for (int i = i0; i < nElem; i += step) {
        int n = i / K, k = i - n*K;
        dst[k*N + segoff + n] = lmul_f(src[i]);
    }
}

// ---------------- phase 0 ----------------
__device__ void transform_all(const Params* __restrict__ P) {
    const int t0 = blockIdx.x * NT + threadIdx.x;
    const int STEP = NB * NT;
    for (int l = 0; l < LL; ++l) {
        xf<128>(P->Wq + l*DD*DD, g_twqkv[l], 384,   0, DD*DD, t0, STEP);
        xf<128>(P->Wk + l*DD*DD, g_twqkv[l], 384, 128, DD*DD, t0, STEP);
        xf<128>(P->Wv + l*DD*DD, g_twqkv[l], 384, 256, DD*DD, t0, STEP);
        xf<128>(P->Wo + l*DD*DD, g_two[l],   128,   0, DD*DD, t0, STEP);
        xf<128>(P->W1 + l*FF*DD, g_tw1[l],   512,   0, FF*DD, t0, STEP);
        xf<512>(P->W2 + l*DD*FF, g_tw2[l],   128,   0, DD*FF, t0, STEP);
    }
    xf<128>(P->Wout, g_twout, 1024, 0, VV*DD, t0, STEP);
    for (int i = t0; i < NROWS*DD; i += STEP) {
        int row = i >> 7, d = i & 127;
        int s = row & (BBS - 1);
        g_x[i] = P->emb[P->tokens[row]*DD + d] + P->pos[s*DD + d];
    }
}

// ---------------- tensor-core GEMM tile: 16 rows x 64 cols, K = 128 ----------
// mma.sync.m16n8k8 tf32. 8 warps, each owns an 8-col strip.
// MODE 0: stage f(X rows). MODE 1: rows = g_x + badd + sum(g_ffp) -> LN ->
//         write g_x (identical across col-tiles) and stage f(LN row).
#define WSS 72
template<int MODE>
__device__ __forceinline__ void gemm_mma(
    const float* __restrict__ X, int ldx, int kbeg,
    const float* __restrict__ W, int N,
    const float* __restrict__ bias, int relu,
    const float* __restrict__ badd, const float* __restrict__ gam,
    const float* __restrict__ bet,
    float* __restrict__ Y, int ldy,
    int row0, int col0,
    float* __restrict__ ws /* 128*WSS */, float* __restrict__ xs /* 16*132 */)
{
    const int tid = threadIdx.x;
    const int lane = tid & 31;
    #pragma unroll
    for (int i = 0; i < 8; ++i) {
        int idx = tid + i*NT;
        int k = idx >> 4, c4 = (idx & 15) << 2;
        *(float4*)(ws + k*WSS + c4) =
            *(const float4*)(W + (size_t)(kbeg + k)*N + col0 + c4);
    }
    #pragma unroll
    for (int i = 0; i < 2; ++i) {
        int r = (tid >> 5) + i*8;
        int k4 = lane * 4;
        if (MODE == 0) {
            float4 v = lmul_f4(*(const float4*)(X + (size_t)(row0 + r)*ldx + kbeg + k4));
            *(float4*)(xs + r*132 + k4) = v;
        } else {
            const int grow = row0 + r;
            float4 u = *(const float4*)(g_x + grow*DD + k4);
            float4 bb = *(const float4*)(badd + k4);
            u.x += bb.x; u.y += bb.y; u.z += bb.z; u.w += bb.w;
            #pragma unroll
            for (int ks = 0; ks < 4; ++ks) {
                float4 p = *(const float4*)(g_ffp[ks] + grow*DD + k4);
                u.x += p.x; u.y += p.y; u.z += p.z; u.w += p.w;
            }
            float s  = (u.x + u.y) + (u.z + u.w);
            float sq = fmaf(u.x, u.x, fmaf(u.y, u.y, fmaf(u.z, u.z, u.w*u.w)));
            #pragma unroll
            for (int o = 16; o; o >>= 1) {
                s  += __shfl_xor_sync(0xffffffffu, s, o);
                sq += __shfl_xor_sync(0xffffffffu, sq, o);
            }
            float mean = s * (1.f/128.f);
            float rs = rsqrtf(sq * (1.f/128.f) - mean*mean + 1e-5f);
            float4 gv  = *(const float4*)(gam + k4);
            float4 bev = *(const float4*)(bet + k4);
            float4 ln;
            ln.x = (u.x - mean)*rs*gv.x + bev.x;
            ln.y = (u.y - mean)*rs*gv.y + bev.y;
            ln.z = (u.z - mean)*rs*gv.z + bev.z;
            ln.w = (u.w - mean)*rs*gv.w + bev.w;
            *(float4*)(g_x + grow*DD + k4) = ln;
            *(float4*)(xs + r*132 + k4) = lmul_f4(ln);
        }
    }
    __syncthreads();

    const int w = tid >> 5;
    const int g = lane >> 2;
    const int t = lane & 3;
    const float* xr0 = xs + g*132;
    const float* xr1 = xs + (g + 8)*132;
    const float* wb  = ws + w*8 + g;
    float c0a=0.f,c1a=0.f,c2a=0.f,c3a=0.f;
    float c0b=0.f,c1b=0.f,c2b=0.f,c3b=0.f;
    #pragma unroll
    for (int k0 = 0; k0 < 128; k0 += 16) {
        unsigned a0 = __float_as_uint(xr0[k0 + t]);
        unsigned a1 = __float_as_uint(xr1[k0 + t]);
        unsigned a2 = __float_as_uint(xr0[k0 + 4 + t]);
        unsigned a3 = __float_as_uint(xr1[k0 + 4 + t]);
        unsigned b0 = __float_as_uint(wb[(k0 + t)*WSS]);
        unsigned b1 = __float_as_uint(wb[(k0 + 4 + t)*WSS]);
        asm volatile(
            "mma.sync.aligned.m16n8k8.row.col.f32.tf32.tf32.f32 "
            "{%0,%1,%2,%3}, {%4,%5,%6,%7}, {%8,%9}, {%0,%1,%2,%3};"
            : "+f"(c0a), "+f"(c1a), "+f"(c2a), "+f"(c3a)
            : "r"(a0), "r"(a1), "r"(a2), "r"(a3), "r"(b0), "r"(b1));
        unsigned a4 = __float_as_uint(xr0[k0 + 8 + t]);
        unsigned a5 = __float_as_uint(xr1[k0 + 8 + t]);
        unsigned a6 = __float_as_uint(xr0[k0 + 12 + t]);
        unsigned a7 = __float_as_uint(xr1[k0 + 12 + t]);
        unsigned b2 = __float_as_uint(wb[(k0 + 8 + t)*WSS]);
        unsigned b3 = __float_as_uint(wb[(k0 + 12 + t)*WSS]);
        asm volatile(
            "mma.sync.aligned.m16n8k8.row.col.f32.tf32.tf32.f32 "
            "{%0,%1,%2,%3}, {%4,%5,%6,%7}, {%8,%9}, {%0,%1,%2,%3};"
            : "+f"(c0b), "+f"(c1b), "+f"(c2b), "+f"(c3b)
            : "r"(a4), "r"(a5), "r"(a6), "r"(a7), "r"(b2), "r"(b3));
    }
    float c0 = c0a + c0b, c1 = c1a + c1b, c2 = c2a + c2b, c3 = c3a + c3b;
    int cl = w*8 + 2*t;
    float b0v = bias ? bias[cl]     : 0.f;
    float b1v = bias ? bias[cl + 1] : 0.f;
    c0 += b0v; c1 += b1v; c2 += b0v; c3 += b1v;
    if (relu) {
        c0 = fmaxf(c0, 0.f); c1 = fmaxf(c1, 0.f);
        c2 = fmaxf(c2, 0.f); c3 = fmaxf(c3, 0.f);
    }
    *(float2*)(Y + (size_t)(row0 + g    )*ldy + col0 + cl) = make_float2(c0, c1);
    *(float2*)(Y + (size_t)(row0 + g + 8)*ldy + col0 + cl) = make_float2(c2, c3);
    __syncthreads();
}

// ---------------- attention + O-proj head-partial tile -----------------------
// tile = (b, h, 8-query block); warp per query (8 warps).
// After softmax*V, applies f() to the attention output (O-proj is an l_mul
// linear!) and computes the 8x128 partial f(att_h) @ f(Wo[h*32:,:]) into
// g_ffp[h]. Wo slice staged into the dead K buffer.
__device__ void attn_tile(
    const float* __restrict__ qkv, const float* __restrict__ Wo /* k-major */,
    int b, int h, int qb, float* __restrict__ sm)
{
    float* ksh = sm;               // 128*33 = 4224 (later reused for Wo slice)
    float* vsh = sm + 4224;        // 128*33
    float* qsh = sm + 8448;        // 8*32 = 256
    float* psh = sm + 8704;        // 8*132 = 1056
    float* ash = sm + 9760;        // 8*33 = 264
    float* wsh = ksh;              // 32*132 = 4224 (fits)
    const int tid = threadIdx.x;
    const int wid = tid >> 5, lane = tid & 31;
    #pragma unroll
    for (int i = 0; i < 4; ++i) {
        int idx = tid + i*NT;       // 0..1023 = 128 rows x 8 float4
        int j = idx >> 3, d4 = (idx & 7) * 4;
        const float* base = qkv + (size_t)(b*BBS + j)*384 + h*DK + d4;
        float4 kk = *(const float4*)(base + 128);
        float4 vv = *(const float4*)(base + 256);
        float* kd = ksh + j*33 + d4;
        kd[0] = kk.x; kd[1] = kk.y; kd[2] = kk.z; kd[3] = kk.w;
        float* vd = vsh + j*33 + d4;
        vd[0] = vv.x; vd[1] = vv.y; vd[2] = vv.z; vd[3] = vv.w;
    }
    {
        int qi = tid >> 5, d = tid & 31;   // 8*32 = 256 = NT
        qsh[tid] = qkv[(size_t)(b*BBS + qb*8 + qi)*384 + h*DK + d];
    }
    __syncthreads();
    // scores (warp per query)
    float qr[32];
    #pragma unroll
    for (int d = 0; d < 32; d += 4) {
        float4 t = *(const float4*)(qsh + wid*32 + d);
        qr[d] = t.x; qr[d+1] = t.y; qr[d+2] = t.z; qr[d+3] = t.w;
    }
    const float* k0 = ksh + (lane     )*33;
    const float* k1 = ksh + (lane + 32)*33;
    const float* k2 = ksh + (lane + 64)*33;
    const float* k3 = ksh + (lane + 96)*33;
    float s0 = 0.f, s1 = 0.f, s2 = 0.f, s3 = 0.f;
    #pragma unroll
    for (int d = 0; d < 32; ++d) {
        float qd = qr[d];
        s0 = fmaf(qd, k0[d], s0);
        s1 = fmaf(qd, k1[d], s1);
        s2 = fmaf(qd, k2[d], s2);
        s3 = fmaf(qd, k3[d], s3);
    }
    const float scale = 0.17677669529663687f;  // 1/sqrt(32)
    s0 *= scale; s1 *= scale; s2 *= scale; s3 *= scale;
    float m = fmaxf(fmaxf(s0, s1), fmaxf(s2, s3));
    #pragma unroll
    for (int o = 16; o; o >>= 1) m = fmaxf(m, __shfl_xor_sync(0xffffffffu, m, o));
    float p0 = __expf(s0 - m), p1 = __expf(s1 - m), p2 = __expf(s2 - m), p3 = __expf(s3 - m);
    float lsum = p0 + p1 + p2 + p3;
    #pragma unroll
    for (int o = 16; o; o >>= 1) lsum += __shfl_xor_sync(0xffffffffu, lsum, o);
    float* pp = psh + wid*132;
    pp[lane     ] = p0;
    pp[lane + 32] = p1;
    pp[lane + 64] = p2;
    pp[lane + 96] = p3;
    __syncthreads();                // K reads done; psh complete
    // cooperative Wo slice load into wsh (= ksh region): 32 d x 128 n
    #pragma unroll
    for (int i = 0; i < 4; ++i) {
        int idx = tid + i*NT;       // 0..1023
        int d = idx >> 5, n4 = (idx & 31) * 4;
        *(float4*)(wsh + d*132 + n4) =
            *(const float4*)(Wo + (size_t)(h*DK + d)*DD + n4);
    }
    // softmax * V (warp per query), then f() for the l_mul O-projection
    {
        float o0 = 0.f, o1 = 0.f, o2 = 0.f, o3 = 0.f;
        #pragma unroll 8
        for (int j = 0; j < 128; j += 4) {
            o0 = fmaf(pp[j+0], vsh[(j+0)*33 + lane], o0);
            o1 = fmaf(pp[j+1], vsh[(j+1)*33 + lane], o1);
            o2 = fmaf(pp[j+2], vsh[(j+2)*33 + lane], o2);
            o3 = fmaf(pp[j+3], vsh[(j+3)*33 + lane], o3);
        }
        ash[wid*33 + lane] = lmul_f(((o0 + o1) + (o2 + o3)) / lsum);
    }
    __syncthreads();
    // O-proj partial: c = tid&127, rg = tid>>7 -> rows rg*4..rg*4+3
    {
        const int c = tid & 127, rg = tid >> 7;
        float a0 = 0.f, a1 = 0.f, a2 = 0.f, a3 = 0.f;
        #pragma unroll 8
        for (int d = 0; d < 32; ++d) {
            float wv = wsh[d*132 + c];
            a0 = fmaf(ash[(rg*4+0)*33 + d], wv, a0);
            a1 = fmaf(ash[(rg*4+1)*33 + d], wv, a1);
            a2 = fmaf(ash[(rg*4+2)*33 + d], wv, a2);
            a3 = fmaf(ash[(rg*4+3)*33 + d], wv, a3);
        }
        float* dst = g_ffp[h] + (size_t)(b*BBS + qb*8 + rg*4)*DD + c;
        dst[0*DD] = a0; dst[1*DD] = a1; dst[2*DD] = a2; dst[3*DD] = a3;
    }
    __syncthreads();
}

// ---------------- the one persistent kernel ----------------
__global__ void __launch_bounds__(NT, 2) model_kernel(Params P) {
    __shared__ __align__(16) float sm[128*WSS + 16*132];   // 45.3KB (attn uses 10KB)
    float* ws = sm;
    float* xs = sm + 128*WSS;
    const int bid = blockIdx.x;

    // P0: weight transforms + embedding
    transform_all(&P);
    gbar();

    for (int l = 0; l < LL; ++l) {
        // P1: QKV fused GEMM — 96 tiles; at l=1 staging applies l0 FF2+res+LN2.
        if (bid < 96) {
            int rt = bid & 15, ct = bid >> 4;
            int col0 = ct * 64;
            int seg = col0 >> 7;
            const float* segb = (seg == 0 ? P.bq : seg == 1 ? P.bk : P.bv)
                                + l*DD + (col0 & 127);
            if (l == 0) {
                gemm_mma<0>(g_x, DD, 0, g_twqkv[l], 384, segb, 0,
                            0, 0, 0, g_qkv, 384, rt*16, col0, ws, xs);
            } else {
                gemm_mma<1>(g_x, DD, 0, g_twqkv[l], 384, segb, 0,
                            P.b2, P.g2, P.be2,
                            g_qkv, 384, rt*16, col0, ws, xs);
            }
        }
        gbar();

        // P2: attention + O-proj head partials — 128 tiles (b, h, 8-query)
        if (bid < 128) {
            int b = bid >> 6, h = (bid >> 4) & 3, qb = bid & 15;
            attn_tile(g_qkv, g_two[l], b, h, qb, sm);
        }
        gbar();

        // P3: FF1 + relu — 128 tiles; staging applies oproj-combine+res+LN1.
        if (bid < 128) {
            int rt = bid & 15, ct = bid >> 4;
            gemm_mma<1>(g_x, DD, 0, g_tw1[l], FF, P.b1 + l*FF + ct*64, 1,
                        P.bo + l*DD, P.g1 + l*DD, P.be1 + l*DD,
                        g_ff, FF, rt*16, ct*64, ws, xs);
        }
        gbar();

        // P4: FF2 k-split partials — 128 tiles (16 rt x 2 col64 x 4 k-chunks)
        if (bid < 128) {
            int rt = bid & 15, ct = (bid >> 4) & 1, kc = bid >> 5;
            gemm_mma<0>(g_ff, FF, kc*128, g_tw2[l], DD, (const float*)0, 0,
                        0, 0, 0, g_ffp[kc], DD, rt*16, ct*64, ws, xs);
        }
        gbar();
    }

    // P5: final vocab projection — 256 tiles; staging applies l1 FF2+res+LN2.
    if (bid < 256) {
        int rt = bid & 15, ct = bid >> 4;
        gemm_mma<1>(g_x, DD, 0, g_twout, VV, P.bout + ct*64, 0,
                    P.b2 + DD, P.g2 + DD, P.be2 + DD,
                    P.out, VV, rt*16, ct*64, ws, xs);
    }
}

extern "C" void kernel_launch(void* const* d_in, const int* in_sizes, int n_in,
                              void* d_out, int out_size) {
    Params P;
    P.tokens = (const int*)  d_in[0];
    P.emb    = (const float*)d_in[1];
    P.pos    = (const float*)d_in[2];
    P.Wq     = (const float*)d_in[3];
    P.bq     = (const float*)d_in[4];
    P.Wk     = (const float*)d_in[5];
    P.bk     = (const float*)d_in[6];
    P.Wv     = (const float*)d_in[7];
    P.bv     = (const float*)d_in[8];
    P.Wo     = (const float*)d_in[9];
    P.bo     = (const float*)d_in[10];
    P.W1     = (const float*)d_in[11];
    P.b1     = (const float*)d_in[12];
    P.W2     = (const float*)d_in[13];
    P.b2     = (const float*)d_in[14];
    P.g1     = (const float*)d_in[15];
    P.be1    = (const float*)d_in[16];
    P.g2     = (const float*)d_in[17];
    P.be2    = (const float*)d_in[18];
    P.Wout   = (const float*)d_in[19];
    P.bout   = (const float*)d_in[20];
    P.out    = (float*)d_out;

    model_kernel<<<NB, NT>>>(P);
}